// round 1
// baseline (speedup 1.0000x reference)
#include <cuda_runtime.h>
#include <math.h>

// Problem constants
#define BB 2
#define CC 256
#define NN 4096
#define HH 4
#define KK 16
#define DD 64
#define EPSBN 1e-5f
#define SCALE 0.125f   // d^-0.5 = 1/8

// ---------------- scratch (device globals; no allocation allowed) ----------------
__device__ float g_q   [BB*CC*NN];        // q   [B][C][N]
__device__ float g_kv  [BB*2*CC*NN];      // kv  [B][2C][N]
__device__ float g_qT  [BB*NN*CC];        // qT  [B][N][C]
__device__ float g_kvT [BB*NN*2*CC];      // kvT [B][N][2C] (first C=k, next C=v)
__device__ float g_ao  [BB*CC*NN];        // attention output [B][C][N]
__device__ float g_x1  [BB*CC*NN];        // after bn1 [B][C][N]
__device__ float g_hbuf[BB*4*CC*NN];      // ffn hidden [B][4C][N]
__device__ int   g_nbr [BB*NN*KK];        // knn indices
__device__ float g_w2h [HH*CC];           // per-head column sums of rp_w2
__device__ float g_rps [CC], g_rpsh[CC];
__device__ float g_bn1s[CC], g_bn1sh[CC];
__device__ float g_bn2s[CC], g_bn2sh[CC];

// ---------------- param prep ----------------
__global__ void prep_kernel(const float* __restrict__ rp_g, const float* __restrict__ rp_b,
                            const float* __restrict__ rp_m, const float* __restrict__ rp_v,
                            const float* __restrict__ rp_w2,
                            const float* __restrict__ b1g, const float* __restrict__ b1b,
                            const float* __restrict__ b1m, const float* __restrict__ b1v,
                            const float* __restrict__ b2g, const float* __restrict__ b2b,
                            const float* __restrict__ b2m, const float* __restrict__ b2v)
{
    int t = threadIdx.x;
    if (t < CC) {
        float s = rp_g[t] * rsqrtf(rp_v[t] + EPSBN);
        g_rps[t]  = s;
        g_rpsh[t] = rp_b[t] - rp_m[t] * s;
        float s1 = b1g[t] * rsqrtf(b1v[t] + EPSBN);
        g_bn1s[t]  = s1;
        g_bn1sh[t] = b1b[t] - b1m[t] * s1;
        float s2 = b2g[t] * rsqrtf(b2v[t] + EPSBN);
        g_bn2s[t]  = s2;
        g_bn2sh[t] = b2b[t] - b2m[t] * s2;
        // per-head column sums of rp_w2 (collapses the C x C bias matmul:
        // only sum over d of h2 enters the logits)
        #pragma unroll
        for (int h = 0; h < HH; h++) {
            float acc = 0.f;
            for (int o = 0; o < DD; o++)
                acc += rp_w2[(h*DD + o)*CC + t];
            g_w2h[h*CC + t] = acc;
        }
    }
}

// ---------------- KNN: warp per query, register top-16 + warp merge ----------------
__global__ void knn_kernel(const float* __restrict__ xyz)
{
    int w = threadIdx.x >> 5, lane = threadIdx.x & 31;
    int g = blockIdx.x * 8 + w;
    int b = g >> 12, n = g & (NN - 1);
    const float* X = xyz + (size_t)b * 3 * NN;
    float qx = X[n], qy = X[NN + n], qz = X[2*NN + n];

    float bk[KK]; int bi[KK];
    #pragma unroll
    for (int i = 0; i < KK; i++) { bk[i] = 1e30f; bi[i] = 0; }
    float wmax = 1e30f; int wpos = 0;

    for (int m = lane; m < NN; m += 32) {
        float px = X[m], py = X[NN + m], pz = X[2*NN + m];
        // key = |p|^2 - 2 q.p  (== dist - |q|^2, monotone in dist)
        float key = fmaf(px, px, fmaf(py, py, pz*pz))
                  - 2.f * fmaf(qx, px, fmaf(qy, py, qz*pz));
        if (key < wmax) {
            #pragma unroll
            for (int i = 0; i < KK; i++)
                if (i == wpos) { bk[i] = key; bi[i] = m; }
            wmax = bk[0]; wpos = 0;
            #pragma unroll
            for (int i = 1; i < KK; i++)
                if (bk[i] > wmax) { wmax = bk[i]; wpos = i; }
        }
    }

    // merge: 16 rounds of warp argmin
    int myNbr = 0;
    for (int r = 0; r < KK; r++) {
        float mv = bk[0]; int mp = 0; int pidx = bi[0];
        #pragma unroll
        for (int i = 1; i < KK; i++)
            if (bk[i] < mv) { mv = bk[i]; mp = i; pidx = bi[i]; }
        int owner = lane;
        #pragma unroll
        for (int off = 16; off > 0; off >>= 1) {
            float ov = __shfl_xor_sync(0xffffffffu, mv, off);
            int   oi = __shfl_xor_sync(0xffffffffu, pidx, off);
            int   oo = __shfl_xor_sync(0xffffffffu, owner, off);
            if (ov < mv || (ov == mv && oo < owner)) { mv = ov; pidx = oi; owner = oo; }
        }
        if (lane == owner) {
            #pragma unroll
            for (int i = 0; i < KK; i++)
                if (i == mp) bk[i] = 1e30f;
        }
        if (lane == r) myNbr = pidx;
    }
    if (lane < KK) g_nbr[(size_t)g * KK + lane] = myNbr;
}

// ---------------- generic tiled fp32 GEMM: Y[b] = W(OxC) * X[b](CxN) + epilogue ----------------
// MODE 0: store; 1: relu(acc+bias); 2: (resid+acc)*s+sh; 3: (acc+bias+resid)*s+sh
template<int MODE>
__global__ __launch_bounds__(256)
void gemm_kernel(const float* __restrict__ W, const float* __restrict__ X,
                 float* __restrict__ Y, int O, int C, int Nn,
                 const float* __restrict__ bias,
                 const float* __restrict__ resid,
                 const float* __restrict__ bns, const float* __restrict__ bnsh)
{
    __shared__ float Ws[16][68];
    __shared__ float Xs[16][64];
    int b = blockIdx.z;
    X += (size_t)b * C * Nn;
    Y += (size_t)b * O * Nn;
    if (MODE >= 2) resid += (size_t)b * O * Nn;

    int tid = threadIdx.x;
    int o0 = blockIdx.y * 64, n0 = blockIdx.x * 64;
    int tx = tid & 15, ty = tid >> 4;
    int kkW = tid & 15, orow = tid >> 4;
    int nnX = tid & 63, krX = tid >> 6;

    float acc[4][4];
    #pragma unroll
    for (int i = 0; i < 4; i++)
        #pragma unroll
        for (int j = 0; j < 4; j++) acc[i][j] = 0.f;

    for (int kt = 0; kt < C; kt += 16) {
        #pragma unroll
        for (int i = 0; i < 4; i++)
            Ws[kkW][orow + 16*i] = W[(size_t)(o0 + orow + 16*i) * C + kt + kkW];
        #pragma unroll
        for (int i = 0; i < 4; i++)
            Xs[krX + 4*i][nnX] = X[(size_t)(kt + krX + 4*i) * Nn + n0 + nnX];
        __syncthreads();
        #pragma unroll
        for (int k = 0; k < 16; k++) {
            float a0 = Ws[k][ty*4+0], a1 = Ws[k][ty*4+1];
            float a2 = Ws[k][ty*4+2], a3 = Ws[k][ty*4+3];
            float4 bv = *reinterpret_cast<const float4*>(&Xs[k][tx*4]);
            acc[0][0] = fmaf(a0, bv.x, acc[0][0]); acc[0][1] = fmaf(a0, bv.y, acc[0][1]);
            acc[0][2] = fmaf(a0, bv.z, acc[0][2]); acc[0][3] = fmaf(a0, bv.w, acc[0][3]);
            acc[1][0] = fmaf(a1, bv.x, acc[1][0]); acc[1][1] = fmaf(a1, bv.y, acc[1][1]);
            acc[1][2] = fmaf(a1, bv.z, acc[1][2]); acc[1][3] = fmaf(a1, bv.w, acc[1][3]);
            acc[2][0] = fmaf(a2, bv.x, acc[2][0]); acc[2][1] = fmaf(a2, bv.y, acc[2][1]);
            acc[2][2] = fmaf(a2, bv.z, acc[2][2]); acc[2][3] = fmaf(a2, bv.w, acc[2][3]);
            acc[3][0] = fmaf(a3, bv.x, acc[3][0]); acc[3][1] = fmaf(a3, bv.y, acc[3][1]);
            acc[3][2] = fmaf(a3, bv.z, acc[3][2]); acc[3][3] = fmaf(a3, bv.w, acc[3][3]);
        }
        __syncthreads();
    }

    #pragma unroll
    for (int i = 0; i < 4; i++) {
        int o = o0 + ty*4 + i;
        int nb = n0 + tx*4;
        float4 r = make_float4(acc[i][0], acc[i][1], acc[i][2], acc[i][3]);
        if (MODE == 1) {
            float bo = bias[o];
            r.x = fmaxf(r.x + bo, 0.f); r.y = fmaxf(r.y + bo, 0.f);
            r.z = fmaxf(r.z + bo, 0.f); r.w = fmaxf(r.w + bo, 0.f);
        } else if (MODE == 2) {
            float s = bns[o], sh = bnsh[o];
            float4 rd = *reinterpret_cast<const float4*>(&resid[(size_t)o * Nn + nb]);
            r.x = (r.x + rd.x) * s + sh; r.y = (r.y + rd.y) * s + sh;
            r.z = (r.z + rd.z) * s + sh; r.w = (r.w + rd.w) * s + sh;
        } else if (MODE == 3) {
            float s = bns[o], sh = bnsh[o], bo = bias[o];
            float4 rd = *reinterpret_cast<const float4*>(&resid[(size_t)o * Nn + nb]);
            r.x = (r.x + bo + rd.x) * s + sh; r.y = (r.y + bo + rd.y) * s + sh;
            r.z = (r.z + bo + rd.z) * s + sh; r.w = (r.w + bo + rd.w) * s + sh;
        }
        *reinterpret_cast<float4*>(&Y[(size_t)o * Nn + nb]) = r;
    }
}

// ---------------- transpose [B][R][N] -> [B][N][R] ----------------
__global__ void transpose_kernel(const float* __restrict__ in, float* __restrict__ out, int R)
{
    __shared__ float t[32][33];
    const float* ip = in  + (size_t)blockIdx.z * R * NN;
    float*       op = out + (size_t)blockIdx.z * NN * R;
    int x = blockIdx.x * 32 + threadIdx.x;      // n
    int y0 = blockIdx.y * 32;                    // r base
    #pragma unroll
    for (int j = 0; j < 32; j += 8)
        t[threadIdx.y + j][threadIdx.x] = ip[(size_t)(y0 + threadIdx.y + j) * NN + x];
    __syncthreads();
    int xo = y0 + threadIdx.x;                   // r
    int yo = blockIdx.x * 32;                    // n base
    #pragma unroll
    for (int j = 0; j < 32; j += 8)
        op[(size_t)(yo + threadIdx.y + j) * R + xo] = t[threadIdx.x][threadIdx.y + j];
}

// ---------------- attention (warp per point) ----------------
__global__ __launch_bounds__(256)
void attn_kernel(const float* __restrict__ xyz, const float* __restrict__ rp_w1)
{
    __shared__ int   sIdx[8][KK];
    __shared__ float sLog[8][HH][KK];
    __shared__ float sOut[CC][9];

    int w = threadIdx.x >> 5, lane = threadIdx.x & 31;
    int g = blockIdx.x * 8 + w;
    int b = g >> 12, n = g & (NN - 1);

    if (lane < KK) sIdx[w][lane] = g_nbr[(size_t)g * KK + lane];
    __syncwarp();

    // hoisted per-lane params, channels c = lane + 32*j (head = j>>1)
    float qreg[8], w1x[8], w1y[8], w1z[8], rps[8], rpsh[8], w2r[HH][8];
    #pragma unroll
    for (int j = 0; j < 8; j++) {
        int c = lane + 32*j;
        qreg[j] = g_qT[(size_t)g * CC + c];
        w1x[j] = rp_w1[c*3 + 0];
        w1y[j] = rp_w1[c*3 + 1];
        w1z[j] = rp_w1[c*3 + 2];
        rps[j]  = g_rps[c];
        rpsh[j] = g_rpsh[c];
        #pragma unroll
        for (int h = 0; h < HH; h++) w2r[h][j] = g_w2h[h*CC + c];
    }
    const float* Xp = xyz + (size_t)b * 3 * NN;
    float cx = Xp[n], cy = Xp[NN + n], cz = Xp[2*NN + n];

    for (int k = 0; k < KK; k++) {
        int m = sIdx[w][k];
        float rx = Xp[m] - cx, ry = Xp[NN + m] - cy, rz = Xp[2*NN + m] - cz;
        const float* kvp = &g_kvT[((size_t)b * NN + m) * (2*CC)];
        float qk[HH]  = {0.f, 0.f, 0.f, 0.f};
        float bia[HH] = {0.f, 0.f, 0.f, 0.f};
        #pragma unroll
        for (int j = 0; j < 8; j++) {
            float kv = kvp[lane + 32*j];
            qk[j >> 1] = fmaf(qreg[j], kv, qk[j >> 1]);
            float raw = fmaf(w1x[j], rx, fmaf(w1y[j], ry, w1z[j]*rz));
            float h1 = fmaxf(fmaf(raw, rps[j], rpsh[j]), 0.f);
            #pragma unroll
            for (int h = 0; h < HH; h++)
                bia[h] = fmaf(w2r[h][j], h1, bia[h]);
        }
        float t4[HH];
        #pragma unroll
        for (int h = 0; h < HH; h++) t4[h] = fmaf(SCALE, qk[h], bia[h]);
        #pragma unroll
        for (int off = 16; off > 0; off >>= 1) {
            #pragma unroll
            for (int h = 0; h < HH; h++)
                t4[h] += __shfl_xor_sync(0xffffffffu, t4[h], off);
        }
        if (lane == 0) {
            #pragma unroll
            for (int h = 0; h < HH; h++) sLog[w][h][k] = t4[h];
        }
    }
    __syncwarp();

    // softmax over K per head (4 lanes, one head each)
    if (lane < HH) {
        float mx = -1e30f;
        #pragma unroll
        for (int k = 0; k < KK; k++) mx = fmaxf(mx, sLog[w][lane][k]);
        float s = 0.f;
        #pragma unroll
        for (int k = 0; k < KK; k++) {
            float e = __expf(sLog[w][lane][k] - mx);
            sLog[w][lane][k] = e;
            s += e;
        }
        float inv = 1.f / s;
        #pragma unroll
        for (int k = 0; k < KK; k++) sLog[w][lane][k] *= inv;
    }
    __syncwarp();

    float acc[8] = {0,0,0,0,0,0,0,0};
    for (int k = 0; k < KK; k++) {
        int m = sIdx[w][k];
        const float* vp = &g_kvT[((size_t)b * NN + m) * (2*CC) + CC];
        #pragma unroll
        for (int j = 0; j < 8; j++)
            acc[j] = fmaf(sLog[w][j >> 1][k], vp[lane + 32*j], acc[j]);
    }
    #pragma unroll
    for (int j = 0; j < 8; j++) sOut[lane + 32*j][w] = acc[j];
    __syncthreads();

    // coalesced-ish block write: thread t -> channel t, 8 consecutive n's
    int t = threadIdx.x;
    int bb = (blockIdx.x * 8) >> 12;
    int n0 = (blockIdx.x * 8) & (NN - 1);
    float4 v0 = make_float4(sOut[t][0], sOut[t][1], sOut[t][2], sOut[t][3]);
    float4 v1 = make_float4(sOut[t][4], sOut[t][5], sOut[t][6], sOut[t][7]);
    float* op = &g_ao[((size_t)bb * CC + t) * NN + n0];
    *reinterpret_cast<float4*>(op)     = v0;
    *reinterpret_cast<float4*>(op + 4) = v1;
}

// ---------------- launch ----------------
extern "C" void kernel_launch(void* const* d_in, const int* in_sizes, int n_in,
                              void* d_out, int out_size)
{
    const float* x      = (const float*)d_in[0];
    const float* xyz    = (const float*)d_in[1];
    const float* Wq     = (const float*)d_in[2];
    const float* Wkv    = (const float*)d_in[3];
    const float* Wproj  = (const float*)d_in[4];
    const float* rp_w1  = (const float*)d_in[5];
    const float* rp_g   = (const float*)d_in[6];
    const float* rp_b   = (const float*)d_in[7];
    const float* rp_m   = (const float*)d_in[8];
    const float* rp_v   = (const float*)d_in[9];
    const float* rp_w2  = (const float*)d_in[10];
    const float* bn1_g  = (const float*)d_in[11];
    const float* bn1_b  = (const float*)d_in[12];
    const float* bn1_m  = (const float*)d_in[13];
    const float* bn1_v  = (const float*)d_in[14];
    const float* bn2_g  = (const float*)d_in[15];
    const float* bn2_b  = (const float*)d_in[16];
    const float* bn2_m  = (const float*)d_in[17];
    const float* bn2_v  = (const float*)d_in[18];
    const float* ffn_w1 = (const float*)d_in[19];
    const float* ffn_b1 = (const float*)d_in[20];
    const float* ffn_w2 = (const float*)d_in[21];
    const float* ffn_b2 = (const float*)d_in[22];
    float* out = (float*)d_out;

    // device-global scratch addresses (queries only; no allocation)
    float *p_q, *p_kv, *p_qT, *p_kvT, *p_ao, *p_x1, *p_h;
    float *p_bn1s, *p_bn1sh, *p_bn2s, *p_bn2sh;
    cudaGetSymbolAddress((void**)&p_q,    g_q);
    cudaGetSymbolAddress((void**)&p_kv,   g_kv);
    cudaGetSymbolAddress((void**)&p_qT,   g_qT);
    cudaGetSymbolAddress((void**)&p_kvT,  g_kvT);
    cudaGetSymbolAddress((void**)&p_ao,   g_ao);
    cudaGetSymbolAddress((void**)&p_x1,   g_x1);
    cudaGetSymbolAddress((void**)&p_h,    g_hbuf);
    cudaGetSymbolAddress((void**)&p_bn1s, g_bn1s);
    cudaGetSymbolAddress((void**)&p_bn1sh,g_bn1sh);
    cudaGetSymbolAddress((void**)&p_bn2s, g_bn2s);
    cudaGetSymbolAddress((void**)&p_bn2sh,g_bn2sh);

    prep_kernel<<<1, 256>>>(rp_g, rp_b, rp_m, rp_v, rp_w2,
                            bn1_g, bn1_b, bn1_m, bn1_v,
                            bn2_g, bn2_b, bn2_m, bn2_v);
    knn_kernel<<<BB*NN/8, 256>>>(xyz);

    // q = Wq @ x ; kv = Wkv @ x
    gemm_kernel<0><<<dim3(NN/64, CC/64, BB), 256>>>(Wq,  x, p_q,  CC,   CC, NN, nullptr, nullptr, nullptr, nullptr);
    gemm_kernel<0><<<dim3(NN/64, 2*CC/64, BB), 256>>>(Wkv, x, p_kv, 2*CC, CC, NN, nullptr, nullptr, nullptr, nullptr);

    transpose_kernel<<<dim3(NN/32, CC/32, BB),   dim3(32,8)>>>(p_q,  p_qT,  CC);
    transpose_kernel<<<dim3(NN/32, 2*CC/32, BB), dim3(32,8)>>>(p_kv, p_kvT, 2*CC);

    attn_kernel<<<BB*NN/8, 256>>>(xyz, rp_w1);

    // x1 = bn1(x + Wproj @ attn_out)
    gemm_kernel<2><<<dim3(NN/64, CC/64, BB), 256>>>(Wproj, p_ao, p_x1, CC, CC, NN,
                                                    nullptr, x, p_bn1s, p_bn1sh);
    // h = relu(ffn_w1 @ x1 + b1)
    gemm_kernel<1><<<dim3(NN/64, 4*CC/64, BB), 256>>>(ffn_w1, p_x1, p_h, 4*CC, CC, NN,
                                                      ffn_b1, nullptr, nullptr, nullptr);
    // out = bn2(x1 + ffn_w2 @ h + b2)
    gemm_kernel<3><<<dim3(NN/64, CC/64, BB), 256>>>(ffn_w2, p_h, out, CC, 4*CC, NN,
                                                    ffn_b2, p_x1, p_bn2s, p_bn2sh);
    (void)in_sizes; (void)n_in; (void)out_size;
}

// round 2
// speedup vs baseline: 1.4601x; 1.4601x over previous
#include <cuda_runtime.h>
#include <math.h>

// Problem constants
#define BB 2
#define CC 256
#define NN 4096
#define HH 4
#define KK 16
#define DD 64
#define EPSBN 1e-5f
#define SCALE 0.125f   // d^-0.5 = 1/8

// ---------------- scratch (device globals; no allocation allowed) ----------------
__device__ float g_q   [BB*CC*NN];        // q   [B][C][N]
__device__ float g_kv  [BB*2*CC*NN];      // kv  [B][2C][N]
__device__ float g_qT  [BB*NN*CC];        // qT  [B][N][C]
__device__ float g_kvT [BB*NN*2*CC];      // kvT [B][N][2C] (first C=k, next C=v)
__device__ float g_ao  [BB*CC*NN];        // attention output [B][C][N]
__device__ float g_x1  [BB*CC*NN];        // after bn1 [B][C][N]
__device__ float g_hbuf[BB*4*CC*NN];      // ffn hidden [B][4C][N]
__device__ int   g_nbr [BB*NN*KK];        // knn indices
__device__ float g_w2h [HH*CC];           // per-head column sums of rp_w2
__device__ float g_rps [CC], g_rpsh[CC];
__device__ float g_bn1s[CC], g_bn1sh[CC];
__device__ float g_bn2s[CC], g_bn2sh[CC];

// ---------------- helpers ----------------
__device__ __forceinline__ unsigned f2tf32(float f) {
    unsigned r;
    asm("cvt.rna.tf32.f32 %0, %1;" : "=r"(r) : "f"(f));
    return r;
}

__device__ __forceinline__ void mma_tf32(float c[4],
                                         const unsigned a[4],
                                         const unsigned b[2]) {
    asm volatile(
        "mma.sync.aligned.m16n8k8.row.col.f32.tf32.tf32.f32 "
        "{%0,%1,%2,%3}, {%4,%5,%6,%7}, {%8,%9}, {%0,%1,%2,%3};"
        : "+f"(c[0]), "+f"(c[1]), "+f"(c[2]), "+f"(c[3])
        : "r"(a[0]), "r"(a[1]), "r"(a[2]), "r"(a[3]),
          "r"(b[0]), "r"(b[1]));
}

// ---------------- param prep ----------------
__global__ void prep_kernel(const float* __restrict__ rp_g, const float* __restrict__ rp_b,
                            const float* __restrict__ rp_m, const float* __restrict__ rp_v,
                            const float* __restrict__ rp_w2,
                            const float* __restrict__ b1g, const float* __restrict__ b1b,
                            const float* __restrict__ b1m, const float* __restrict__ b1v,
                            const float* __restrict__ b2g, const float* __restrict__ b2b,
                            const float* __restrict__ b2m, const float* __restrict__ b2v)
{
    int t = threadIdx.x;
    if (t < CC) {
        float s = rp_g[t] * rsqrtf(rp_v[t] + EPSBN);
        g_rps[t]  = s;
        g_rpsh[t] = rp_b[t] - rp_m[t] * s;
        float s1 = b1g[t] * rsqrtf(b1v[t] + EPSBN);
        g_bn1s[t]  = s1;
        g_bn1sh[t] = b1b[t] - b1m[t] * s1;
        float s2 = b2g[t] * rsqrtf(b2v[t] + EPSBN);
        g_bn2s[t]  = s2;
        g_bn2sh[t] = b2b[t] - b2m[t] * s2;
        #pragma unroll
        for (int h = 0; h < HH; h++) {
            float acc = 0.f;
            for (int o = 0; o < DD; o++)
                acc += rp_w2[(h*DD + o)*CC + t];
            g_w2h[h*CC + t] = acc;
        }
    }
}

// ---------------- KNN: warp per query, register top-16 + warp merge ----------------
__global__ void knn_kernel(const float* __restrict__ xyz)
{
    int w = threadIdx.x >> 5, lane = threadIdx.x & 31;
    int g = blockIdx.x * 8 + w;
    int b = g >> 12, n = g & (NN - 1);
    const float* X = xyz + (size_t)b * 3 * NN;
    float qx = X[n], qy = X[NN + n], qz = X[2*NN + n];

    float bk[KK]; int bi[KK];
    #pragma unroll
    for (int i = 0; i < KK; i++) { bk[i] = 1e30f; bi[i] = 0; }
    float wmax = 1e30f; int wpos = 0;

    for (int m = lane; m < NN; m += 32) {
        float px = X[m], py = X[NN + m], pz = X[2*NN + m];
        float key = fmaf(px, px, fmaf(py, py, pz*pz))
                  - 2.f * fmaf(qx, px, fmaf(qy, py, qz*pz));
        if (key < wmax) {
            #pragma unroll
            for (int i = 0; i < KK; i++)
                if (i == wpos) { bk[i] = key; bi[i] = m; }
            wmax = bk[0]; wpos = 0;
            #pragma unroll
            for (int i = 1; i < KK; i++)
                if (bk[i] > wmax) { wmax = bk[i]; wpos = i; }
        }
    }

    int myNbr = 0;
    for (int r = 0; r < KK; r++) {
        float mv = bk[0]; int mp = 0; int pidx = bi[0];
        #pragma unroll
        for (int i = 1; i < KK; i++)
            if (bk[i] < mv) { mv = bk[i]; mp = i; pidx = bi[i]; }
        int owner = lane;
        #pragma unroll
        for (int off = 16; off > 0; off >>= 1) {
            float ov = __shfl_xor_sync(0xffffffffu, mv, off);
            int   oi = __shfl_xor_sync(0xffffffffu, pidx, off);
            int   oo = __shfl_xor_sync(0xffffffffu, owner, off);
            if (ov < mv || (ov == mv && oo < owner)) { mv = ov; pidx = oi; owner = oo; }
        }
        if (lane == owner) {
            #pragma unroll
            for (int i = 0; i < KK; i++)
                if (i == mp) bk[i] = 1e30f;
        }
        if (lane == r) myNbr = pidx;
    }
    if (lane < KK) g_nbr[(size_t)g * KK + lane] = myNbr;
}

// ---------------- tf32 tensor-core GEMM: Y[b] = W(OxC) * X[b](CxN) + epilogue ----------------
// 128x128 block tile, BK=32, 8 warps of 64x32, mma m16n8k8 tf32.
// MODE 0: store; 1: relu(acc+bias); 2: (resid+acc)*s+sh; 3: (acc+bias+resid)*s+sh
#define LDA 36
#define LDB 136
template<int MODE>
__global__ __launch_bounds__(256, 2)
void gemm_tc(const float* __restrict__ W, const float* __restrict__ X,
             float* __restrict__ Y, int O, int C, int Nn,
             const float* __restrict__ bias,
             const float* __restrict__ resid,
             const float* __restrict__ bns, const float* __restrict__ bnsh)
{
    __shared__ unsigned As[128 * LDA];   // [m][k], tf32 bits
    __shared__ unsigned Bs[32 * LDB];    // [k][n], tf32 bits

    int b = blockIdx.z;
    X += (size_t)b * C * Nn;
    Y += (size_t)b * O * Nn;
    if (MODE >= 2) resid += (size_t)b * O * Nn;

    const int tid   = threadIdx.x;
    const int lane  = tid & 31;
    const int wid   = tid >> 5;
    const int warpM = wid >> 2;          // 0..1
    const int warpN = wid & 3;           // 0..3
    const int lr    = lane >> 2;         // 0..7
    const int lc    = lane & 3;          // 0..3
    const int o0    = blockIdx.y * 128;
    const int n0    = blockIdx.x * 128;

    float acc[4][4][4];
    #pragma unroll
    for (int mt = 0; mt < 4; mt++)
        #pragma unroll
        for (int nt = 0; nt < 4; nt++)
            #pragma unroll
            for (int r = 0; r < 4; r++) acc[mt][nt][r] = 0.f;

    for (int kt = 0; kt < C; kt += 32) {
        // load A tile: 128 rows x 32 k
        #pragma unroll
        for (int i = 0; i < 4; i++) {
            int f   = tid + 256 * i;
            int row = f >> 3;
            int kq  = (f & 7) * 4;
            float4 wv = *reinterpret_cast<const float4*>(
                            &W[(size_t)(o0 + row) * C + kt + kq]);
            unsigned* p = &As[row * LDA + kq];
            p[0] = f2tf32(wv.x); p[1] = f2tf32(wv.y);
            p[2] = f2tf32(wv.z); p[3] = f2tf32(wv.w);
        }
        // load B tile: 32 k x 128 n
        #pragma unroll
        for (int i = 0; i < 4; i++) {
            int f   = tid + 256 * i;
            int row = f >> 5;
            int nq  = (f & 31) * 4;
            float4 xv = *reinterpret_cast<const float4*>(
                            &X[(size_t)(kt + row) * Nn + n0 + nq]);
            unsigned* p = &Bs[row * LDB + nq];
            p[0] = f2tf32(xv.x); p[1] = f2tf32(xv.y);
            p[2] = f2tf32(xv.z); p[3] = f2tf32(xv.w);
        }
        __syncthreads();

        #pragma unroll
        for (int kk = 0; kk < 4; kk++) {
            const int kb = kk * 8;
            unsigned afr[4][4], bfr[4][2];
            #pragma unroll
            for (int mt = 0; mt < 4; mt++) {
                int r = warpM * 64 + mt * 16 + lr;
                afr[mt][0] = As[r       * LDA + kb + lc];
                afr[mt][1] = As[(r + 8) * LDA + kb + lc];
                afr[mt][2] = As[r       * LDA + kb + 4 + lc];
                afr[mt][3] = As[(r + 8) * LDA + kb + 4 + lc];
            }
            #pragma unroll
            for (int nt = 0; nt < 4; nt++) {
                int cb = warpN * 32 + nt * 8 + lr;
                bfr[nt][0] = Bs[(kb + lc)     * LDB + cb];
                bfr[nt][1] = Bs[(kb + 4 + lc) * LDB + cb];
            }
            #pragma unroll
            for (int mt = 0; mt < 4; mt++)
                #pragma unroll
                for (int nt = 0; nt < 4; nt++)
                    mma_tf32(acc[mt][nt], afr[mt], bfr[nt]);
        }
        __syncthreads();
    }

    // epilogue
    #pragma unroll
    for (int mt = 0; mt < 4; mt++) {
        int o = o0 + warpM * 64 + mt * 16 + lr;
        #pragma unroll
        for (int nt = 0; nt < 4; nt++) {
            int n = n0 + warpN * 32 + nt * 8 + lc * 2;
            float2 p0 = make_float2(acc[mt][nt][0], acc[mt][nt][1]);
            float2 p1 = make_float2(acc[mt][nt][2], acc[mt][nt][3]);
            size_t i0 = (size_t)o * Nn + n;
            size_t i1 = (size_t)(o + 8) * Nn + n;
            if (MODE == 1) {
                float b0 = bias[o], b1 = bias[o + 8];
                p0.x = fmaxf(p0.x + b0, 0.f); p0.y = fmaxf(p0.y + b0, 0.f);
                p1.x = fmaxf(p1.x + b1, 0.f); p1.y = fmaxf(p1.y + b1, 0.f);
            } else if (MODE == 2) {
                float s0 = bns[o], h0 = bnsh[o];
                float s1 = bns[o + 8], h1 = bnsh[o + 8];
                float2 r0 = *reinterpret_cast<const float2*>(&resid[i0]);
                float2 r1 = *reinterpret_cast<const float2*>(&resid[i1]);
                p0.x = (p0.x + r0.x) * s0 + h0; p0.y = (p0.y + r0.y) * s0 + h0;
                p1.x = (p1.x + r1.x) * s1 + h1; p1.y = (p1.y + r1.y) * s1 + h1;
            } else if (MODE == 3) {
                float s0 = bns[o], h0 = bnsh[o], bo0 = bias[o];
                float s1 = bns[o + 8], h1 = bnsh[o + 8], bo1 = bias[o + 8];
                float2 r0 = *reinterpret_cast<const float2*>(&resid[i0]);
                float2 r1 = *reinterpret_cast<const float2*>(&resid[i1]);
                p0.x = (p0.x + bo0 + r0.x) * s0 + h0; p0.y = (p0.y + bo0 + r0.y) * s0 + h0;
                p1.x = (p1.x + bo1 + r1.x) * s1 + h1; p1.y = (p1.y + bo1 + r1.y) * s1 + h1;
            }
            *reinterpret_cast<float2*>(&Y[i0]) = p0;
            *reinterpret_cast<float2*>(&Y[i1]) = p1;
        }
    }
}

// ---------------- transpose [B][R][N] -> [B][N][R] ----------------
__global__ void transpose_kernel(const float* __restrict__ in, float* __restrict__ out, int R)
{
    __shared__ float t[32][33];
    const float* ip = in  + (size_t)blockIdx.z * R * NN;
    float*       op = out + (size_t)blockIdx.z * NN * R;
    int x = blockIdx.x * 32 + threadIdx.x;
    int y0 = blockIdx.y * 32;
    #pragma unroll
    for (int j = 0; j < 32; j += 8)
        t[threadIdx.y + j][threadIdx.x] = ip[(size_t)(y0 + threadIdx.y + j) * NN + x];
    __syncthreads();
    int xo = y0 + threadIdx.x;
    int yo = blockIdx.x * 32;
    #pragma unroll
    for (int j = 0; j < 32; j += 8)
        op[(size_t)(yo + threadIdx.y + j) * R + xo] = t[threadIdx.x][threadIdx.y + j];
}

// ---------------- attention (warp per point) ----------------
__global__ __launch_bounds__(256)
void attn_kernel(const float* __restrict__ xyz, const float* __restrict__ rp_w1)
{
    __shared__ int   sIdx[8][KK];
    __shared__ float sLog[8][HH][KK];
    __shared__ float sOut[CC][9];

    int w = threadIdx.x >> 5, lane = threadIdx.x & 31;
    int g = blockIdx.x * 8 + w;
    int b = g >> 12, n = g & (NN - 1);

    if (lane < KK) sIdx[w][lane] = g_nbr[(size_t)g * KK + lane];
    __syncwarp();

    float qreg[8], w1x[8], w1y[8], w1z[8], rps[8], rpsh[8], w2r[HH][8];
    #pragma unroll
    for (int j = 0; j < 8; j++) {
        int c = lane + 32*j;
        qreg[j] = g_qT[(size_t)g * CC + c];
        w1x[j] = rp_w1[c*3 + 0];
        w1y[j] = rp_w1[c*3 + 1];
        w1z[j] = rp_w1[c*3 + 2];
        rps[j]  = g_rps[c];
        rpsh[j] = g_rpsh[c];
        #pragma unroll
        for (int h = 0; h < HH; h++) w2r[h][j] = g_w2h[h*CC + c];
    }
    const float* Xp = xyz + (size_t)b * 3 * NN;
    float cx = Xp[n], cy = Xp[NN + n], cz = Xp[2*NN + n];

    for (int k = 0; k < KK; k++) {
        int m = sIdx[w][k];
        float rx = Xp[m] - cx, ry = Xp[NN + m] - cy, rz = Xp[2*NN + m] - cz;
        const float* kvp = &g_kvT[((size_t)b * NN + m) * (2*CC)];
        float qk[HH]  = {0.f, 0.f, 0.f, 0.f};
        float bia[HH] = {0.f, 0.f, 0.f, 0.f};
        #pragma unroll
        for (int j = 0; j < 8; j++) {
            float kv = kvp[lane + 32*j];
            qk[j >> 1] = fmaf(qreg[j], kv, qk[j >> 1]);
            float raw = fmaf(w1x[j], rx, fmaf(w1y[j], ry, w1z[j]*rz));
            float h1 = fmaxf(fmaf(raw, rps[j], rpsh[j]), 0.f);
            #pragma unroll
            for (int h = 0; h < HH; h++)
                bia[h] = fmaf(w2r[h][j], h1, bia[h]);
        }
        float t4[HH];
        #pragma unroll
        for (int h = 0; h < HH; h++) t4[h] = fmaf(SCALE, qk[h], bia[h]);
        #pragma unroll
        for (int off = 16; off > 0; off >>= 1) {
            #pragma unroll
            for (int h = 0; h < HH; h++)
                t4[h] += __shfl_xor_sync(0xffffffffu, t4[h], off);
        }
        if (lane == 0) {
            #pragma unroll
            for (int h = 0; h < HH; h++) sLog[w][h][k] = t4[h];
        }
    }
    __syncwarp();

    if (lane < HH) {
        float mx = -1e30f;
        #pragma unroll
        for (int k = 0; k < KK; k++) mx = fmaxf(mx, sLog[w][lane][k]);
        float s = 0.f;
        #pragma unroll
        for (int k = 0; k < KK; k++) {
            float e = __expf(sLog[w][lane][k] - mx);
            sLog[w][lane][k] = e;
            s += e;
        }
        float inv = 1.f / s;
        #pragma unroll
        for (int k = 0; k < KK; k++) sLog[w][lane][k] *= inv;
    }
    __syncwarp();

    float acc[8] = {0,0,0,0,0,0,0,0};
    for (int k = 0; k < KK; k++) {
        int m = sIdx[w][k];
        const float* vp = &g_kvT[((size_t)b * NN + m) * (2*CC) + CC];
        #pragma unroll
        for (int j = 0; j < 8; j++)
            acc[j] = fmaf(sLog[w][j >> 1][k], vp[lane + 32*j], acc[j]);
    }
    #pragma unroll
    for (int j = 0; j < 8; j++) sOut[lane + 32*j][w] = acc[j];
    __syncthreads();

    int t = threadIdx.x;
    int bb = (blockIdx.x * 8) >> 12;
    int n0 = (blockIdx.x * 8) & (NN - 1);
    float4 v0 = make_float4(sOut[t][0], sOut[t][1], sOut[t][2], sOut[t][3]);
    float4 v1 = make_float4(sOut[t][4], sOut[t][5], sOut[t][6], sOut[t][7]);
    float* op = &g_ao[((size_t)bb * CC + t) * NN + n0];
    *reinterpret_cast<float4*>(op)     = v0;
    *reinterpret_cast<float4*>(op + 4) = v1;
}

// ---------------- launch ----------------
extern "C" void kernel_launch(void* const* d_in, const int* in_sizes, int n_in,
                              void* d_out, int out_size)
{
    const float* x      = (const float*)d_in[0];
    const float* xyz    = (const float*)d_in[1];
    const float* Wq     = (const float*)d_in[2];
    const float* Wkv    = (const float*)d_in[3];
    const float* Wproj  = (const float*)d_in[4];
    const float* rp_w1  = (const float*)d_in[5];
    const float* rp_g   = (const float*)d_in[6];
    const float* rp_b   = (const float*)d_in[7];
    const float* rp_m   = (const float*)d_in[8];
    const float* rp_v   = (const float*)d_in[9];
    const float* rp_w2  = (const float*)d_in[10];
    const float* bn1_g  = (const float*)d_in[11];
    const float* bn1_b  = (const float*)d_in[12];
    const float* bn1_m  = (const float*)d_in[13];
    const float* bn1_v  = (const float*)d_in[14];
    const float* bn2_g  = (const float*)d_in[15];
    const float* bn2_b  = (const float*)d_in[16];
    const float* bn2_m  = (const float*)d_in[17];
    const float* bn2_v  = (const float*)d_in[18];
    const float* ffn_w1 = (const float*)d_in[19];
    const float* ffn_b1 = (const float*)d_in[20];
    const float* ffn_w2 = (const float*)d_in[21];
    const float* ffn_b2 = (const float*)d_in[22];
    float* out = (float*)d_out;

    float *p_q, *p_kv, *p_qT, *p_kvT, *p_ao, *p_x1, *p_h;
    float *p_bn1s, *p_bn1sh, *p_bn2s, *p_bn2sh;
    cudaGetSymbolAddress((void**)&p_q,    g_q);
    cudaGetSymbolAddress((void**)&p_kv,   g_kv);
    cudaGetSymbolAddress((void**)&p_qT,   g_qT);
    cudaGetSymbolAddress((void**)&p_kvT,  g_kvT);
    cudaGetSymbolAddress((void**)&p_ao,   g_ao);
    cudaGetSymbolAddress((void**)&p_x1,   g_x1);
    cudaGetSymbolAddress((void**)&p_h,    g_hbuf);
    cudaGetSymbolAddress((void**)&p_bn1s, g_bn1s);
    cudaGetSymbolAddress((void**)&p_bn1sh,g_bn1sh);
    cudaGetSymbolAddress((void**)&p_bn2s, g_bn2s);
    cudaGetSymbolAddress((void**)&p_bn2sh,g_bn2sh);

    prep_kernel<<<1, 256>>>(rp_g, rp_b, rp_m, rp_v, rp_w2,
                            bn1_g, bn1_b, bn1_m, bn1_v,
                            bn2_g, bn2_b, bn2_m, bn2_v);
    knn_kernel<<<BB*NN/8, 256>>>(xyz);

    // q = Wq @ x ; kv = Wkv @ x
    gemm_tc<0><<<dim3(NN/128, CC/128, BB), 256>>>(Wq,  x, p_q,  CC,   CC, NN, nullptr, nullptr, nullptr, nullptr);
    gemm_tc<0><<<dim3(NN/128, 2*CC/128, BB), 256>>>(Wkv, x, p_kv, 2*CC, CC, NN, nullptr, nullptr, nullptr, nullptr);

    transpose_kernel<<<dim3(NN/32, CC/32, BB),   dim3(32,8)>>>(p_q,  p_qT,  CC);
    transpose_kernel<<<dim3(NN/32, 2*CC/32, BB), dim3(32,8)>>>(p_kv, p_kvT, 2*CC);

    attn_kernel<<<BB*NN/8, 256>>>(xyz, rp_w1);

    // x1 = bn1(x + Wproj @ attn_out)
    gemm_tc<2><<<dim3(NN/128, CC/128, BB), 256>>>(Wproj, p_ao, p_x1, CC, CC, NN,
                                                  nullptr, x, p_bn1s, p_bn1sh);
    // h = relu(ffn_w1 @ x1 + b1)
    gemm_tc<1><<<dim3(NN/128, 4*CC/128, BB), 256>>>(ffn_w1, p_x1, p_h, 4*CC, CC, NN,
                                                    ffn_b1, nullptr, nullptr, nullptr);
    // out = bn2(x1 + ffn_w2 @ h + b2)
    gemm_tc<3><<<dim3(NN/128, CC/128, BB), 256>>>(ffn_w2, p_h, out, CC, 4*CC, NN,
                                                  ffn_b2, p_x1, p_bn2s, p_bn2sh);
    (void)in_sizes; (void)n_in; (void)out_size;
}

// round 3
// speedup vs baseline: 2.1034x; 1.4405x over previous
#include <cuda_runtime.h>
#include <math.h>

// Problem constants
#define BB 2
#define CC 256
#define NN 4096
#define HH 4
#define KK 16
#define DD 64
#define EPSBN 1e-5f
#define SCALE 0.125f   // d^-0.5 = 1/8

// ---------------- scratch (device globals; no allocation allowed) ----------------
__device__ float g_qT  [BB*NN*CC];        // qT  [B][N][C]
__device__ float g_kvT [BB*NN*2*CC];      // kvT [B][N][2C] (first C=k, next C=v)
__device__ float g_ao  [BB*CC*NN];        // attention output [B][C][N]
__device__ float g_x1  [BB*CC*NN];        // after bn1 [B][C][N]
__device__ float g_hbuf[BB*4*CC*NN];      // ffn hidden [B][4C][N]
__device__ int   g_nbr [BB*NN*KK];        // knn indices
__device__ float g_w2h [HH*CC];           // per-head column sums of rp_w2
__device__ float g_rps [CC], g_rpsh[CC];
__device__ float g_bn1s[CC], g_bn1sh[CC];
__device__ float g_bn2s[CC], g_bn2sh[CC];

// ---------------- helpers ----------------
__device__ __forceinline__ void mma_tf32(float c[4],
                                         const unsigned a[4],
                                         const unsigned b[2]) {
    asm volatile(
        "mma.sync.aligned.m16n8k8.row.col.f32.tf32.tf32.f32 "
        "{%0,%1,%2,%3}, {%4,%5,%6,%7}, {%8,%9}, {%0,%1,%2,%3};"
        : "+f"(c[0]), "+f"(c[1]), "+f"(c[2]), "+f"(c[3])
        : "r"(a[0]), "r"(a[1]), "r"(a[2]), "r"(a[3]),
          "r"(b[0]), "r"(b[1]));
}

__device__ __forceinline__ void cp16(unsigned* smem_dst, const float* gsrc) {
    unsigned u = (unsigned)__cvta_generic_to_shared(smem_dst);
    asm volatile("cp.async.cg.shared.global [%0], [%1], 16;" :: "r"(u), "l"(gsrc));
}

// ---------------- param prep (5 blocks) ----------------
__global__ void prep_kernel(const float* __restrict__ rp_g, const float* __restrict__ rp_b,
                            const float* __restrict__ rp_m, const float* __restrict__ rp_v,
                            const float* __restrict__ rp_w2,
                            const float* __restrict__ b1g, const float* __restrict__ b1b,
                            const float* __restrict__ b1m, const float* __restrict__ b1v,
                            const float* __restrict__ b2g, const float* __restrict__ b2b,
                            const float* __restrict__ b2m, const float* __restrict__ b2v)
{
    int t = threadIdx.x;
    int blk = blockIdx.x;
    if (blk < HH) {
        // per-head column sums of rp_w2 (collapses the C x C bias matmul)
        float acc = 0.f;
        #pragma unroll 8
        for (int o = 0; o < DD; o++)
            acc += rp_w2[(blk*DD + o)*CC + t];
        g_w2h[blk*CC + t] = acc;
    } else {
        float s = rp_g[t] * rsqrtf(rp_v[t] + EPSBN);
        g_rps[t]  = s;
        g_rpsh[t] = rp_b[t] - rp_m[t] * s;
        float s1 = b1g[t] * rsqrtf(b1v[t] + EPSBN);
        g_bn1s[t]  = s1;
        g_bn1sh[t] = b1b[t] - b1m[t] * s1;
        float s2 = b2g[t] * rsqrtf(b2v[t] + EPSBN);
        g_bn2s[t]  = s2;
        g_bn2sh[t] = b2b[t] - b2m[t] * s2;
    }
}

// ---------------- KNN: warp per query, warp-shared threshold + sorted insert ----------------
// Safety of the W prune: W = min over lanes of (lane's 16th-best). Every lane's
// 16th-best is >= the warp-global 16th-best, and the min over lanes is too
// (each lane holds 16 elements <= its own worst => warp 16th <= every lane worst).
// So any candidate >= W cannot be in the warp top-16 and may be dropped.
__global__ void knn_kernel(const float* __restrict__ xyz)
{
    int w = threadIdx.x >> 5, lane = threadIdx.x & 31;
    int g = blockIdx.x * 8 + w;
    int b = g >> 12, n = g & (NN - 1);
    const float* X = xyz + (size_t)b * 3 * NN;
    float qx = X[n], qy = X[NN + n], qz = X[2*NN + n];

    float bk[KK]; int bi[KK];          // sorted ascending; bk[15] = worst
    #pragma unroll
    for (int i = 0; i < KK; i++) { bk[i] = 1e30f; bi[i] = 0; }
    float W = 1e30f;

    for (int j = 0; j < NN/32; j++) {
        int m = lane + 32*j;
        float px = X[m], py = X[NN + m], pz = X[2*NN + m];
        // key = |p|^2 - 2 q.p  (== dist - |q|^2, monotone in dist)
        float key = fmaf(px, px, fmaf(py, py, pz*pz))
                  - 2.f * fmaf(qx, px, fmaf(qy, py, qz*pz));
        if (__any_sync(0xffffffffu, key < W)) {
            if (key < W) {
                bk[KK-1] = key; bi[KK-1] = m;
                #pragma unroll
                for (int i = KK-1; i > 0; i--) {
                    float a = bk[i-1], c = bk[i];
                    int   ai = bi[i-1], ci = bi[i];
                    bool sw = c < a;
                    bk[i-1] = sw ? c : a;  bk[i] = sw ? a : c;
                    bi[i-1] = sw ? ci : ai; bi[i] = sw ? ai : ci;
                }
            }
            float wv = bk[KK-1];
            #pragma unroll
            for (int off = 16; off > 0; off >>= 1)
                wv = fminf(wv, __shfl_xor_sync(0xffffffffu, wv, off));
            W = wv;
        }
    }

    // merge: 16 rounds of warp argmin over sorted heads
    int myNbr = 0;
    for (int r = 0; r < KK; r++) {
        float mv = bk[0]; int pidx = bi[0]; int owner = lane;
        #pragma unroll
        for (int off = 16; off > 0; off >>= 1) {
            float ov = __shfl_xor_sync(0xffffffffu, mv, off);
            int   oi = __shfl_xor_sync(0xffffffffu, pidx, off);
            int   oo = __shfl_xor_sync(0xffffffffu, owner, off);
            if (ov < mv || (ov == mv && oo < owner)) { mv = ov; pidx = oi; owner = oo; }
        }
        if (lane == owner) {
            #pragma unroll
            for (int i = 0; i < KK-1; i++) { bk[i] = bk[i+1]; bi[i] = bi[i+1]; }
            bk[KK-1] = 1e30f;
        }
        if (lane == r) myNbr = pidx;
    }
    if (lane < KK) g_nbr[(size_t)g * KK + lane] = myNbr;
}

// ---------------- tf32 tensor-core GEMM with cp.async double buffer ----------------
// Y[b] = W(OxC) * X[b](CxN). 128x128 block tile, BK=32, 8 warps of 64x32.
// Raw fp32 bits fed to mma.tf32 (HW truncates mantissa) -> no cvt, direct LDGSTS.
// MODE 1: relu(acc+bias); 2: (resid+acc)*s+sh; 3: (acc+bias+resid)*s+sh;
// MODE 4: transposed store Y_T[n*O + o]  (for q / kv)
#define LDA 36
#define LDB 136
#define STAGE_WORDS (128*LDA + 32*LDB)
#define GEMM_SMEM_BYTES (2*STAGE_WORDS*4)

template<int MODE>
__global__ __launch_bounds__(256, 2)
void gemm_tc(const float* __restrict__ W, const float* __restrict__ X,
             float* __restrict__ Y, int O, int C, int Nn,
             const float* __restrict__ bias,
             const float* __restrict__ resid,
             const float* __restrict__ bns, const float* __restrict__ bnsh)
{
    extern __shared__ unsigned sm[];

    int b = blockIdx.z;
    X += (size_t)b * C * Nn;
    Y += (size_t)b * (size_t)O * Nn;   // same total size either layout
    if (MODE == 2 || MODE == 3) resid += (size_t)b * O * Nn;

    const int tid   = threadIdx.x;
    const int lane  = tid & 31;
    const int wid   = tid >> 5;
    const int warpM = wid >> 2;          // 0..1
    const int warpN = wid & 3;           // 0..3
    const int lr    = lane >> 2;         // 0..7
    const int lc    = lane & 3;          // 0..3
    const int o0    = blockIdx.y * 128;
    const int n0    = blockIdx.x * 128;

    // per-thread load coordinates
    const int arow = tid >> 3, akq = (tid & 7) * 4;     // +32 rows per i
    const int brow = tid >> 5, bnq = (tid & 31) * 4;    // +8 rows per i

    float acc[4][4][4];
    #pragma unroll
    for (int mt = 0; mt < 4; mt++)
        #pragma unroll
        for (int nt = 0; nt < 4; nt++)
            #pragma unroll
            for (int r = 0; r < 4; r++) acc[mt][nt][r] = 0.f;

    const int ntiles = C >> 5;

    // prologue: stage 0 <- kt 0
    {
        unsigned* As = sm; unsigned* Bs = sm + 128*LDA;
        #pragma unroll
        for (int i = 0; i < 4; i++)
            cp16(&As[(arow + 32*i) * LDA + akq], &W[(size_t)(o0 + arow + 32*i) * C + akq]);
        #pragma unroll
        for (int i = 0; i < 4; i++)
            cp16(&Bs[(brow + 8*i) * LDB + bnq], &X[(size_t)(brow + 8*i) * Nn + n0 + bnq]);
        asm volatile("cp.async.commit_group;");
    }

    for (int it = 0; it < ntiles; it++) {
        int s = it & 1;
        if (it + 1 < ntiles) {
            int ktn = (it + 1) << 5;
            unsigned* As = sm + (s^1)*STAGE_WORDS; unsigned* Bs = As + 128*LDA;
            #pragma unroll
            for (int i = 0; i < 4; i++)
                cp16(&As[(arow + 32*i) * LDA + akq], &W[(size_t)(o0 + arow + 32*i) * C + ktn + akq]);
            #pragma unroll
            for (int i = 0; i < 4; i++)
                cp16(&Bs[(brow + 8*i) * LDB + bnq], &X[(size_t)(ktn + brow + 8*i) * Nn + n0 + bnq]);
        }
        asm volatile("cp.async.commit_group;");
        asm volatile("cp.async.wait_group %0;" :: "n"(1));
        __syncthreads();

        const unsigned* As = sm + s*STAGE_WORDS;
        const unsigned* Bs = As + 128*LDA;
        #pragma unroll
        for (int kk = 0; kk < 4; kk++) {
            const int kb = kk * 8;
            unsigned afr[4][4], bfr[4][2];
            #pragma unroll
            for (int mt = 0; mt < 4; mt++) {
                int r = warpM * 64 + mt * 16 + lr;
                afr[mt][0] = As[r       * LDA + kb + lc];
                afr[mt][1] = As[(r + 8) * LDA + kb + lc];
                afr[mt][2] = As[r       * LDA + kb + 4 + lc];
                afr[mt][3] = As[(r + 8) * LDA + kb + 4 + lc];
            }
            #pragma unroll
            for (int nt = 0; nt < 4; nt++) {
                int cb = warpN * 32 + nt * 8 + lr;
                bfr[nt][0] = Bs[(kb + lc)     * LDB + cb];
                bfr[nt][1] = Bs[(kb + 4 + lc) * LDB + cb];
            }
            #pragma unroll
            for (int mt = 0; mt < 4; mt++)
                #pragma unroll
                for (int nt = 0; nt < 4; nt++)
                    mma_tf32(acc[mt][nt], afr[mt], bfr[nt]);
        }
        __syncthreads();   // stage s is reloaded next iteration
    }

    // epilogue
    #pragma unroll
    for (int mt = 0; mt < 4; mt++) {
        int o = o0 + warpM * 64 + mt * 16 + lr;
        #pragma unroll
        for (int nt = 0; nt < 4; nt++) {
            int n = n0 + warpN * 32 + nt * 8 + lc * 2;
            if (MODE == 4) {
                Y[(size_t)n       * O + o]     = acc[mt][nt][0];
                Y[(size_t)(n + 1) * O + o]     = acc[mt][nt][1];
                Y[(size_t)n       * O + o + 8] = acc[mt][nt][2];
                Y[(size_t)(n + 1) * O + o + 8] = acc[mt][nt][3];
                continue;
            }
            float2 p0 = make_float2(acc[mt][nt][0], acc[mt][nt][1]);
            float2 p1 = make_float2(acc[mt][nt][2], acc[mt][nt][3]);
            size_t i0 = (size_t)o * Nn + n;
            size_t i1 = (size_t)(o + 8) * Nn + n;
            if (MODE == 1) {
                float b0 = bias[o], b1 = bias[o + 8];
                p0.x = fmaxf(p0.x + b0, 0.f); p0.y = fmaxf(p0.y + b0, 0.f);
                p1.x = fmaxf(p1.x + b1, 0.f); p1.y = fmaxf(p1.y + b1, 0.f);
            } else if (MODE == 2) {
                float s0 = bns[o], h0 = bnsh[o];
                float s1 = bns[o + 8], h1 = bnsh[o + 8];
                float2 r0 = *reinterpret_cast<const float2*>(&resid[i0]);
                float2 r1 = *reinterpret_cast<const float2*>(&resid[i1]);
                p0.x = (p0.x + r0.x) * s0 + h0; p0.y = (p0.y + r0.y) * s0 + h0;
                p1.x = (p1.x + r1.x) * s1 + h1; p1.y = (p1.y + r1.y) * s1 + h1;
            } else if (MODE == 3) {
                float s0 = bns[o], h0 = bnsh[o], bo0 = bias[o];
                float s1 = bns[o + 8], h1 = bnsh[o + 8], bo1 = bias[o + 8];
                float2 r0 = *reinterpret_cast<const float2*>(&resid[i0]);
                float2 r1 = *reinterpret_cast<const float2*>(&resid[i1]);
                p0.x = (p0.x + bo0 + r0.x) * s0 + h0; p0.y = (p0.y + bo0 + r0.y) * s0 + h0;
                p1.x = (p1.x + bo1 + r1.x) * s1 + h1; p1.y = (p1.y + bo1 + r1.y) * s1 + h1;
            }
            *reinterpret_cast<float2*>(&Y[i0]) = p0;
            *reinterpret_cast<float2*>(&Y[i1]) = p1;
        }
    }
}

// ---------------- attention (warp per point) ----------------
__global__ __launch_bounds__(256)
void attn_kernel(const float* __restrict__ xyz, const float* __restrict__ rp_w1)
{
    __shared__ int   sIdx[8][KK];
    __shared__ float sLog[8][HH][KK];
    __shared__ float sOut[CC][9];

    int w = threadIdx.x >> 5, lane = threadIdx.x & 31;
    int g = blockIdx.x * 8 + w;
    int b = g >> 12, n = g & (NN - 1);

    if (lane < KK) sIdx[w][lane] = g_nbr[(size_t)g * KK + lane];
    __syncwarp();

    float qreg[8], w1x[8], w1y[8], w1z[8], rps[8], rpsh[8], w2r[HH][8];
    #pragma unroll
    for (int j = 0; j < 8; j++) {
        int c = lane + 32*j;
        qreg[j] = g_qT[(size_t)g * CC + c];
        w1x[j] = rp_w1[c*3 + 0];
        w1y[j] = rp_w1[c*3 + 1];
        w1z[j] = rp_w1[c*3 + 2];
        rps[j]  = g_rps[c];
        rpsh[j] = g_rpsh[c];
        #pragma unroll
        for (int h = 0; h < HH; h++) w2r[h][j] = g_w2h[h*CC + c];
    }
    const float* Xp = xyz + (size_t)b * 3 * NN;
    float cx = Xp[n], cy = Xp[NN + n], cz = Xp[2*NN + n];

    for (int k = 0; k < KK; k++) {
        int m = sIdx[w][k];
        float rx = Xp[m] - cx, ry = Xp[NN + m] - cy, rz = Xp[2*NN + m] - cz;
        const float* kvp = &g_kvT[((size_t)b * NN + m) * (2*CC)];
        float qk[HH]  = {0.f, 0.f, 0.f, 0.f};
        float bia[HH] = {0.f, 0.f, 0.f, 0.f};
        #pragma unroll
        for (int j = 0; j < 8; j++) {
            float kv = kvp[lane + 32*j];
            qk[j >> 1] = fmaf(qreg[j], kv, qk[j >> 1]);
            float raw = fmaf(w1x[j], rx, fmaf(w1y[j], ry, w1z[j]*rz));
            float h1 = fmaxf(fmaf(raw, rps[j], rpsh[j]), 0.f);
            #pragma unroll
            for (int h = 0; h < HH; h++)
                bia[h] = fmaf(w2r[h][j], h1, bia[h]);
        }
        float t4[HH];
        #pragma unroll
        for (int h = 0; h < HH; h++) t4[h] = fmaf(SCALE, qk[h], bia[h]);
        #pragma unroll
        for (int off = 16; off > 0; off >>= 1) {
            #pragma unroll
            for (int h = 0; h < HH; h++)
                t4[h] += __shfl_xor_sync(0xffffffffu, t4[h], off);
        }
        if (lane == 0) {
            #pragma unroll
            for (int h = 0; h < HH; h++) sLog[w][h][k] = t4[h];
        }
    }
    __syncwarp();

    if (lane < HH) {
        float mx = -1e30f;
        #pragma unroll
        for (int k = 0; k < KK; k++) mx = fmaxf(mx, sLog[w][lane][k]);
        float s = 0.f;
        #pragma unroll
        for (int k = 0; k < KK; k++) {
            float e = __expf(sLog[w][lane][k] - mx);
            sLog[w][lane][k] = e;
            s += e;
        }
        float inv = 1.f / s;
        #pragma unroll
        for (int k = 0; k < KK; k++) sLog[w][lane][k] *= inv;
    }
    __syncwarp();

    float acc[8] = {0,0,0,0,0,0,0,0};
    for (int k = 0; k < KK; k++) {
        int m = sIdx[w][k];
        const float* vp = &g_kvT[((size_t)b * NN + m) * (2*CC) + CC];
        #pragma unroll
        for (int j = 0; j < 8; j++)
            acc[j] = fmaf(sLog[w][j >> 1][k], vp[lane + 32*j], acc[j]);
    }
    #pragma unroll
    for (int j = 0; j < 8; j++) sOut[lane + 32*j][w] = acc[j];
    __syncthreads();

    int t = threadIdx.x;
    int bb = (blockIdx.x * 8) >> 12;
    int n0 = (blockIdx.x * 8) & (NN - 1);
    float4 v0 = make_float4(sOut[t][0], sOut[t][1], sOut[t][2], sOut[t][3]);
    float4 v1 = make_float4(sOut[t][4], sOut[t][5], sOut[t][6], sOut[t][7]);
    float* op = &g_ao[((size_t)bb * CC + t) * NN + n0];
    *reinterpret_cast<float4*>(op)     = v0;
    *reinterpret_cast<float4*>(op + 4) = v1;
}

// ---------------- launch ----------------
extern "C" void kernel_launch(void* const* d_in, const int* in_sizes, int n_in,
                              void* d_out, int out_size)
{
    const float* x      = (const float*)d_in[0];
    const float* xyz    = (const float*)d_in[1];
    const float* Wq     = (const float*)d_in[2];
    const float* Wkv    = (const float*)d_in[3];
    const float* Wproj  = (const float*)d_in[4];
    const float* rp_w1  = (const float*)d_in[5];
    const float* rp_g   = (const float*)d_in[6];
    const float* rp_b   = (const float*)d_in[7];
    const float* rp_m   = (const float*)d_in[8];
    const float* rp_v   = (const float*)d_in[9];
    const float* rp_w2  = (const float*)d_in[10];
    const float* bn1_g  = (const float*)d_in[11];
    const float* bn1_b  = (const float*)d_in[12];
    const float* bn1_m  = (const float*)d_in[13];
    const float* bn1_v  = (const float*)d_in[14];
    const float* bn2_g  = (const float*)d_in[15];
    const float* bn2_b  = (const float*)d_in[16];
    const float* bn2_m  = (const float*)d_in[17];
    const float* bn2_v  = (const float*)d_in[18];
    const float* ffn_w1 = (const float*)d_in[19];
    const float* ffn_b1 = (const float*)d_in[20];
    const float* ffn_w2 = (const float*)d_in[21];
    const float* ffn_b2 = (const float*)d_in[22];
    float* out = (float*)d_out;

    float *p_qT, *p_kvT, *p_ao, *p_x1, *p_h;
    float *p_bn1s, *p_bn1sh, *p_bn2s, *p_bn2sh;
    cudaGetSymbolAddress((void**)&p_qT,   g_qT);
    cudaGetSymbolAddress((void**)&p_kvT,  g_kvT);
    cudaGetSymbolAddress((void**)&p_ao,   g_ao);
    cudaGetSymbolAddress((void**)&p_x1,   g_x1);
    cudaGetSymbolAddress((void**)&p_h,    g_hbuf);
    cudaGetSymbolAddress((void**)&p_bn1s, g_bn1s);
    cudaGetSymbolAddress((void**)&p_bn1sh,g_bn1sh);
    cudaGetSymbolAddress((void**)&p_bn2s, g_bn2s);
    cudaGetSymbolAddress((void**)&p_bn2sh,g_bn2sh);

    // allow 70KB dynamic smem (idempotent; safe every call)
    cudaFuncSetAttribute(gemm_tc<1>, cudaFuncAttributeMaxDynamicSharedMemorySize, GEMM_SMEM_BYTES);
    cudaFuncSetAttribute(gemm_tc<2>, cudaFuncAttributeMaxDynamicSharedMemorySize, GEMM_SMEM_BYTES);
    cudaFuncSetAttribute(gemm_tc<3>, cudaFuncAttributeMaxDynamicSharedMemorySize, GEMM_SMEM_BYTES);
    cudaFuncSetAttribute(gemm_tc<4>, cudaFuncAttributeMaxDynamicSharedMemorySize, GEMM_SMEM_BYTES);

    prep_kernel<<<5, 256>>>(rp_g, rp_b, rp_m, rp_v, rp_w2,
                            bn1_g, bn1_b, bn1_m, bn1_v,
                            bn2_g, bn2_b, bn2_m, bn2_v);
    knn_kernel<<<BB*NN/8, 256>>>(xyz);

    // qT = (Wq @ x)^T ; kvT = (Wkv @ x)^T   (transposed-store epilogue)
    gemm_tc<4><<<dim3(NN/128, CC/128, BB),   256, GEMM_SMEM_BYTES>>>(Wq,  x, p_qT,  CC,   CC, NN, nullptr, nullptr, nullptr, nullptr);
    gemm_tc<4><<<dim3(NN/128, 2*CC/128, BB), 256, GEMM_SMEM_BYTES>>>(Wkv, x, p_kvT, 2*CC, CC, NN, nullptr, nullptr, nullptr, nullptr);

    attn_kernel<<<BB*NN/8, 256>>>(xyz, rp_w1);

    // x1 = bn1(x + Wproj @ attn_out)
    gemm_tc<2><<<dim3(NN/128, CC/128, BB), 256, GEMM_SMEM_BYTES>>>(Wproj, p_ao, p_x1, CC, CC, NN,
                                                                   nullptr, x, p_bn1s, p_bn1sh);
    // h = relu(ffn_w1 @ x1 + b1)
    gemm_tc<1><<<dim3(NN/128, 4*CC/128, BB), 256, GEMM_SMEM_BYTES>>>(ffn_w1, p_x1, p_h, 4*CC, CC, NN,
                                                                     ffn_b1, nullptr, nullptr, nullptr);
    // out = bn2(x1 + ffn_w2 @ h + b2)
    gemm_tc<3><<<dim3(NN/128, CC/128, BB), 256, GEMM_SMEM_BYTES>>>(ffn_w2, p_h, out, CC, 4*CC, NN,
                                                                   ffn_b2, p_x1, p_bn2s, p_bn2sh);
    (void)in_sizes; (void)n_in; (void)out_size;
}

// round 4
// speedup vs baseline: 2.1465x; 1.0205x over previous
#include <cuda_runtime.h>
#include <math.h>

// Problem constants
#define BB 2
#define CC 256
#define NN 4096
#define HH 4
#define KK 16
#define DD 64
#define EPSBN 1e-5f
#define SCALE 0.125f   // d^-0.5 = 1/8

// ---------------- scratch (device globals; no allocation allowed) ----------------
__device__ float g_qT  [BB*NN*CC];        // qT  [B][N][C]
__device__ float g_kvT [BB*NN*2*CC];      // kvT [B][N][2C] (first C=k, next C=v)
__device__ float g_ao  [BB*CC*NN];        // attention output [B][C][N]
__device__ float g_x1  [BB*CC*NN];        // after bn1 [B][C][N]
__device__ float g_hbuf[BB*4*CC*NN];      // ffn hidden [B][4C][N]
__device__ int   g_nbr [BB*NN*KK];        // knn indices
__device__ float g_w2h [HH*CC];           // per-head column sums of rp_w2
__device__ float g_rps [CC], g_rpsh[CC];
__device__ float g_bn1s[CC], g_bn1sh[CC];
__device__ float g_bn2s[CC], g_bn2sh[CC];

// ---------------- helpers ----------------
__device__ __forceinline__ void mma_tf32(float c[4],
                                         const unsigned a[4],
                                         const unsigned b[2]) {
    asm volatile(
        "mma.sync.aligned.m16n8k8.row.col.f32.tf32.tf32.f32 "
        "{%0,%1,%2,%3}, {%4,%5,%6,%7}, {%8,%9}, {%0,%1,%2,%3};"
        : "+f"(c[0]), "+f"(c[1]), "+f"(c[2]), "+f"(c[3])
        : "r"(a[0]), "r"(a[1]), "r"(a[2]), "r"(a[3]),
          "r"(b[0]), "r"(b[1]));
}

__device__ __forceinline__ void cp16(unsigned* smem_dst, const float* gsrc) {
    unsigned u = (unsigned)__cvta_generic_to_shared(smem_dst);
    asm volatile("cp.async.cg.shared.global [%0], [%1], 16;" :: "r"(u), "l"(gsrc));
}

// ---------------- param prep (5 blocks) ----------------
__global__ void prep_kernel(const float* __restrict__ rp_g, const float* __restrict__ rp_b,
                            const float* __restrict__ rp_m, const float* __restrict__ rp_v,
                            const float* __restrict__ rp_w2,
                            const float* __restrict__ b1g, const float* __restrict__ b1b,
                            const float* __restrict__ b1m, const float* __restrict__ b1v,
                            const float* __restrict__ b2g, const float* __restrict__ b2b,
                            const float* __restrict__ b2m, const float* __restrict__ b2v)
{
    int t = threadIdx.x;
    int blk = blockIdx.x;
    if (blk < HH) {
        float acc = 0.f;
        #pragma unroll 8
        for (int o = 0; o < DD; o++)
            acc += rp_w2[(blk*DD + o)*CC + t];
        g_w2h[blk*CC + t] = acc;
    } else {
        float s = rp_g[t] * rsqrtf(rp_v[t] + EPSBN);
        g_rps[t]  = s;
        g_rpsh[t] = rp_b[t] - rp_m[t] * s;
        float s1 = b1g[t] * rsqrtf(b1v[t] + EPSBN);
        g_bn1s[t]  = s1;
        g_bn1sh[t] = b1b[t] - b1m[t] * s1;
        float s2 = b2g[t] * rsqrtf(b2v[t] + EPSBN);
        g_bn2s[t]  = s2;
        g_bn2sh[t] = b2b[t] - b2m[t] * s2;
    }
}

// ---------------- KNN: warp per query, warp-shared threshold + sorted insert ----------------
__global__ void knn_kernel(const float* __restrict__ xyz)
{
    int w = threadIdx.x >> 5, lane = threadIdx.x & 31;
    int g = blockIdx.x * 8 + w;
    int b = g >> 12, n = g & (NN - 1);
    const float* X = xyz + (size_t)b * 3 * NN;
    float qx = X[n], qy = X[NN + n], qz = X[2*NN + n];

    float bk[KK]; int bi[KK];          // sorted ascending; bk[15] = worst
    #pragma unroll
    for (int i = 0; i < KK; i++) { bk[i] = 1e30f; bi[i] = 0; }
    float W = 1e30f;

    for (int j = 0; j < NN/32; j++) {
        int m = lane + 32*j;
        float px = X[m], py = X[NN + m], pz = X[2*NN + m];
        float key = fmaf(px, px, fmaf(py, py, pz*pz))
                  - 2.f * fmaf(qx, px, fmaf(qy, py, qz*pz));
        if (__any_sync(0xffffffffu, key < W)) {
            if (key < W) {
                bk[KK-1] = key; bi[KK-1] = m;
                #pragma unroll
                for (int i = KK-1; i > 0; i--) {
                    float a = bk[i-1], c = bk[i];
                    int   ai = bi[i-1], ci = bi[i];
                    bool sw = c < a;
                    bk[i-1] = sw ? c : a;  bk[i] = sw ? a : c;
                    bi[i-1] = sw ? ci : ai; bi[i] = sw ? ai : ci;
                }
            }
            float wv = bk[KK-1];
            #pragma unroll
            for (int off = 16; off > 0; off >>= 1)
                wv = fminf(wv, __shfl_xor_sync(0xffffffffu, wv, off));
            W = wv;
        }
    }

    int myNbr = 0;
    for (int r = 0; r < KK; r++) {
        float mv = bk[0]; int pidx = bi[0]; int owner = lane;
        #pragma unroll
        for (int off = 16; off > 0; off >>= 1) {
            float ov = __shfl_xor_sync(0xffffffffu, mv, off);
            int   oi = __shfl_xor_sync(0xffffffffu, pidx, off);
            int   oo = __shfl_xor_sync(0xffffffffu, owner, off);
            if (ov < mv || (ov == mv && oo < owner)) { mv = ov; pidx = oi; owner = oo; }
        }
        if (lane == owner) {
            #pragma unroll
            for (int i = 0; i < KK-1; i++) { bk[i] = bk[i+1]; bi[i] = bi[i+1]; }
            bk[KK-1] = 1e30f;
        }
        if (lane == r) myNbr = pidx;
    }
    if (lane < KK) g_nbr[(size_t)g * KK + lane] = myNbr;
}

// ---------------- tf32 tensor-core GEMM, 3-stage cp.async, 1 sync/iter ----------------
// Y[b] = W(OxC) * X[b](CxN). 128x128 block tile, BK=32, 8 warps of 64x32.
// MODE 1: relu(acc+bias); 2: (resid+acc)*s+sh; 3: (acc+bias+resid)*s+sh;
// MODE 4: fused q/kv, transposed store; blockIdx.y<2 -> W/qT (stride CC),
//         else W2/kvT (stride 2CC). W2,Y2 used only in MODE 4.
#define LDA 36
#define LDB 136
#define STAGE_WORDS (128*LDA + 32*LDB)
#define GEMM_SMEM_BYTES (3*STAGE_WORDS*4)

template<int MODE>
__global__ __launch_bounds__(256, 1)
void gemm_tc(const float* __restrict__ W, const float* __restrict__ X,
             float* __restrict__ Y, int O, int C, int Nn,
             const float* __restrict__ bias,
             const float* __restrict__ resid,
             const float* __restrict__ bns, const float* __restrict__ bnsh,
             const float* __restrict__ W2, float* __restrict__ Y2)
{
    extern __shared__ unsigned sm[];

    const int b = blockIdx.z;
    X += (size_t)b * C * Nn;

    const float* Wp;
    float* Yp;            // MODE 4 output base (batch included)
    int Ostr = 0, oB;
    if (MODE == 4) {
        int by = blockIdx.y;
        if (by < 2) { Wp = W;  Yp = Y  + (size_t)b * NN * CC;    Ostr = CC;    oB = by * 128; }
        else        { Wp = W2; Yp = Y2 + (size_t)b * NN * 2*CC;  Ostr = 2*CC;  oB = (by - 2) * 128; }
    } else {
        Wp = W; oB = blockIdx.y * 128;
        Y += (size_t)b * O * Nn;
        Yp = Y;
        if (MODE == 2 || MODE == 3) resid += (size_t)b * O * Nn;
    }

    const int tid   = threadIdx.x;
    const int lane  = tid & 31;
    const int wid   = tid >> 5;
    const int warpM = wid >> 2;          // 0..1
    const int warpN = wid & 3;           // 0..3
    const int lr    = lane >> 2;         // 0..7
    const int lc    = lane & 3;          // 0..3
    const int n0    = blockIdx.x * 128;

    const int arow = tid >> 3, akq = (tid & 7) * 4;     // +32 rows per i
    const int brow = tid >> 5, bnq = (tid & 31) * 4;    // +8 rows per i

    float acc[4][4][4];
    #pragma unroll
    for (int mt = 0; mt < 4; mt++)
        #pragma unroll
        for (int nt = 0; nt < 4; nt++)
            #pragma unroll
            for (int r = 0; r < 4; r++) acc[mt][nt][r] = 0.f;

    const int ntiles = C >> 5;

    // prologue: stages 0,1
    #pragma unroll
    for (int p = 0; p < 2; p++) {
        unsigned* As = sm + p*STAGE_WORDS; unsigned* Bs = As + 128*LDA;
        int kt = p << 5;
        #pragma unroll
        for (int i = 0; i < 4; i++)
            cp16(&As[(arow + 32*i) * LDA + akq], &Wp[(size_t)(oB + arow + 32*i) * C + kt + akq]);
        #pragma unroll
        for (int i = 0; i < 4; i++)
            cp16(&Bs[(brow + 8*i) * LDB + bnq], &X[(size_t)(kt + brow + 8*i) * Nn + n0 + bnq]);
        asm volatile("cp.async.commit_group;");
    }

    int sNext = 2;   // stage slot for it+2
    for (int it = 0; it < ntiles; it++) {
        asm volatile("cp.async.wait_group %0;" :: "n"(1));
        __syncthreads();

        if (it + 2 < ntiles) {
            int ktn = (it + 2) << 5;
            unsigned* As = sm + sNext*STAGE_WORDS; unsigned* Bs = As + 128*LDA;
            #pragma unroll
            for (int i = 0; i < 4; i++)
                cp16(&As[(arow + 32*i) * LDA + akq], &Wp[(size_t)(oB + arow + 32*i) * C + ktn + akq]);
            #pragma unroll
            for (int i = 0; i < 4; i++)
                cp16(&Bs[(brow + 8*i) * LDB + bnq], &X[(size_t)(ktn + brow + 8*i) * Nn + n0 + bnq]);
        }
        asm volatile("cp.async.commit_group;");

        int sCur = sNext + 1; if (sCur >= 3) sCur -= 3;   // == it % 3
        const unsigned* As = sm + sCur*STAGE_WORDS;
        const unsigned* Bs = As + 128*LDA;
        #pragma unroll
        for (int kk = 0; kk < 4; kk++) {
            const int kb = kk * 8;
            unsigned afr[4][4], bfr[4][2];
            #pragma unroll
            for (int mt = 0; mt < 4; mt++) {
                int r = warpM * 64 + mt * 16 + lr;
                afr[mt][0] = As[r       * LDA + kb + lc];
                afr[mt][1] = As[(r + 8) * LDA + kb + lc];
                afr[mt][2] = As[r       * LDA + kb + 4 + lc];
                afr[mt][3] = As[(r + 8) * LDA + kb + 4 + lc];
            }
            #pragma unroll
            for (int nt = 0; nt < 4; nt++) {
                int cb = warpN * 32 + nt * 8 + lr;
                bfr[nt][0] = Bs[(kb + lc)     * LDB + cb];
                bfr[nt][1] = Bs[(kb + 4 + lc) * LDB + cb];
            }
            #pragma unroll
            for (int mt = 0; mt < 4; mt++)
                #pragma unroll
                for (int nt = 0; nt < 4; nt++)
                    mma_tf32(acc[mt][nt], afr[mt], bfr[nt]);
        }
        sNext = sCur;   // slot it%3 becomes the (it+3) target == next iteration's it+2
    }

    // epilogue
    #pragma unroll
    for (int mt = 0; mt < 4; mt++) {
        int o = oB + warpM * 64 + mt * 16 + lr;
        #pragma unroll
        for (int nt = 0; nt < 4; nt++) {
            int n = n0 + warpN * 32 + nt * 8 + lc * 2;
            if (MODE == 4) {
                Yp[(size_t)n       * Ostr + o]     = acc[mt][nt][0];
                Yp[(size_t)(n + 1) * Ostr + o]     = acc[mt][nt][1];
                Yp[(size_t)n       * Ostr + o + 8] = acc[mt][nt][2];
                Yp[(size_t)(n + 1) * Ostr + o + 8] = acc[mt][nt][3];
                continue;
            }
            float2 p0 = make_float2(acc[mt][nt][0], acc[mt][nt][1]);
            float2 p1 = make_float2(acc[mt][nt][2], acc[mt][nt][3]);
            size_t i0 = (size_t)o * Nn + n;
            size_t i1 = (size_t)(o + 8) * Nn + n;
            if (MODE == 1) {
                float b0 = bias[o], b1 = bias[o + 8];
                p0.x = fmaxf(p0.x + b0, 0.f); p0.y = fmaxf(p0.y + b0, 0.f);
                p1.x = fmaxf(p1.x + b1, 0.f); p1.y = fmaxf(p1.y + b1, 0.f);
            } else if (MODE == 2) {
                float s0 = bns[o], h0 = bnsh[o];
                float s1 = bns[o + 8], h1 = bnsh[o + 8];
                float2 r0 = *reinterpret_cast<const float2*>(&resid[i0]);
                float2 r1 = *reinterpret_cast<const float2*>(&resid[i1]);
                p0.x = (p0.x + r0.x) * s0 + h0; p0.y = (p0.y + r0.y) * s0 + h0;
                p1.x = (p1.x + r1.x) * s1 + h1; p1.y = (p1.y + r1.y) * s1 + h1;
            } else if (MODE == 3) {
                float s0 = bns[o], h0 = bnsh[o], bo0 = bias[o];
                float s1 = bns[o + 8], h1 = bnsh[o + 8], bo1 = bias[o + 8];
                float2 r0 = *reinterpret_cast<const float2*>(&resid[i0]);
                float2 r1 = *reinterpret_cast<const float2*>(&resid[i1]);
                p0.x = (p0.x + bo0 + r0.x) * s0 + h0; p0.y = (p0.y + bo0 + r0.y) * s0 + h0;
                p1.x = (p1.x + bo1 + r1.x) * s1 + h1; p1.y = (p1.y + bo1 + r1.y) * s1 + h1;
            }
            *reinterpret_cast<float2*>(&Yp[i0]) = p0;
            *reinterpret_cast<float2*>(&Yp[i1]) = p1;
        }
    }
}

// ---------------- attention (warp per point) ----------------
__global__ __launch_bounds__(256)
void attn_kernel(const float* __restrict__ xyz, const float* __restrict__ rp_w1)
{
    __shared__ int   sIdx[8][KK];
    __shared__ float sLog[8][HH][KK];
    __shared__ float sOut[CC][9];

    int w = threadIdx.x >> 5, lane = threadIdx.x & 31;
    int g = blockIdx.x * 8 + w;
    int b = g >> 12, n = g & (NN - 1);

    if (lane < KK) sIdx[w][lane] = g_nbr[(size_t)g * KK + lane];
    __syncwarp();

    float qreg[8], w1x[8], w1y[8], w1z[8], rps[8], rpsh[8], w2r[HH][8];
    #pragma unroll
    for (int j = 0; j < 8; j++) {
        int c = lane + 32*j;
        qreg[j] = g_qT[(size_t)g * CC + c];
        w1x[j] = rp_w1[c*3 + 0];
        w1y[j] = rp_w1[c*3 + 1];
        w1z[j] = rp_w1[c*3 + 2];
        rps[j]  = g_rps[c];
        rpsh[j] = g_rpsh[c];
        #pragma unroll
        for (int h = 0; h < HH; h++) w2r[h][j] = g_w2h[h*CC + c];
    }
    const float* Xp = xyz + (size_t)b * 3 * NN;
    float cx = Xp[n], cy = Xp[NN + n], cz = Xp[2*NN + n];

    for (int k = 0; k < KK; k++) {
        int m = sIdx[w][k];
        float rx = Xp[m] - cx, ry = Xp[NN + m] - cy, rz = Xp[2*NN + m] - cz;
        const float* kvp = &g_kvT[((size_t)b * NN + m) * (2*CC)];
        float qk[HH]  = {0.f, 0.f, 0.f, 0.f};
        float bia[HH] = {0.f, 0.f, 0.f, 0.f};
        #pragma unroll
        for (int j = 0; j < 8; j++) {
            float kv = kvp[lane + 32*j];
            qk[j >> 1] = fmaf(qreg[j], kv, qk[j >> 1]);
            float raw = fmaf(w1x[j], rx, fmaf(w1y[j], ry, w1z[j]*rz));
            float h1 = fmaxf(fmaf(raw, rps[j], rpsh[j]), 0.f);
            #pragma unroll
            for (int h = 0; h < HH; h++)
                bia[h] = fmaf(w2r[h][j], h1, bia[h]);
        }
        float t4[HH];
        #pragma unroll
        for (int h = 0; h < HH; h++) t4[h] = fmaf(SCALE, qk[h], bia[h]);
        #pragma unroll
        for (int off = 16; off > 0; off >>= 1) {
            #pragma unroll
            for (int h = 0; h < HH; h++)
                t4[h] += __shfl_xor_sync(0xffffffffu, t4[h], off);
        }
        if (lane == 0) {
            #pragma unroll
            for (int h = 0; h < HH; h++) sLog[w][h][k] = t4[h];
        }
    }
    __syncwarp();

    if (lane < HH) {
        float mx = -1e30f;
        #pragma unroll
        for (int k = 0; k < KK; k++) mx = fmaxf(mx, sLog[w][lane][k]);
        float s = 0.f;
        #pragma unroll
        for (int k = 0; k < KK; k++) {
            float e = __expf(sLog[w][lane][k] - mx);
            sLog[w][lane][k] = e;
            s += e;
        }
        float inv = 1.f / s;
        #pragma unroll
        for (int k = 0; k < KK; k++) sLog[w][lane][k] *= inv;
    }
    __syncwarp();

    float acc[8] = {0,0,0,0,0,0,0,0};
    for (int k = 0; k < KK; k++) {
        int m = sIdx[w][k];
        const float* vp = &g_kvT[((size_t)b * NN + m) * (2*CC) + CC];
        #pragma unroll
        for (int j = 0; j < 8; j++)
            acc[j] = fmaf(sLog[w][j >> 1][k], vp[lane + 32*j], acc[j]);
    }
    #pragma unroll
    for (int j = 0; j < 8; j++) sOut[lane + 32*j][w] = acc[j];
    __syncthreads();

    int t = threadIdx.x;
    int bb = (blockIdx.x * 8) >> 12;
    int n0 = (blockIdx.x * 8) & (NN - 1);
    float4 v0 = make_float4(sOut[t][0], sOut[t][1], sOut[t][2], sOut[t][3]);
    float4 v1 = make_float4(sOut[t][4], sOut[t][5], sOut[t][6], sOut[t][7]);
    float* op = &g_ao[((size_t)bb * CC + t) * NN + n0];
    *reinterpret_cast<float4*>(op)     = v0;
    *reinterpret_cast<float4*>(op + 4) = v1;
}

// ---------------- launch ----------------
extern "C" void kernel_launch(void* const* d_in, const int* in_sizes, int n_in,
                              void* d_out, int out_size)
{
    const float* x      = (const float*)d_in[0];
    const float* xyz    = (const float*)d_in[1];
    const float* Wq     = (const float*)d_in[2];
    const float* Wkv    = (const float*)d_in[3];
    const float* Wproj  = (const float*)d_in[4];
    const float* rp_w1  = (const float*)d_in[5];
    const float* rp_g   = (const float*)d_in[6];
    const float* rp_b   = (const float*)d_in[7];
    const float* rp_m   = (const float*)d_in[8];
    const float* rp_v   = (const float*)d_in[9];
    const float* rp_w2  = (const float*)d_in[10];
    const float* bn1_g  = (const float*)d_in[11];
    const float* bn1_b  = (const float*)d_in[12];
    const float* bn1_m  = (const float*)d_in[13];
    const float* bn1_v  = (const float*)d_in[14];
    const float* bn2_g  = (const float*)d_in[15];
    const float* bn2_b  = (const float*)d_in[16];
    const float* bn2_m  = (const float*)d_in[17];
    const float* bn2_v  = (const float*)d_in[18];
    const float* ffn_w1 = (const float*)d_in[19];
    const float* ffn_b1 = (const float*)d_in[20];
    const float* ffn_w2 = (const float*)d_in[21];
    const float* ffn_b2 = (const float*)d_in[22];
    float* out = (float*)d_out;

    float *p_qT, *p_kvT, *p_ao, *p_x1, *p_h;
    float *p_bn1s, *p_bn1sh, *p_bn2s, *p_bn2sh;
    cudaGetSymbolAddress((void**)&p_qT,   g_qT);
    cudaGetSymbolAddress((void**)&p_kvT,  g_kvT);
    cudaGetSymbolAddress((void**)&p_ao,   g_ao);
    cudaGetSymbolAddress((void**)&p_x1,   g_x1);
    cudaGetSymbolAddress((void**)&p_h,    g_hbuf);
    cudaGetSymbolAddress((void**)&p_bn1s, g_bn1s);
    cudaGetSymbolAddress((void**)&p_bn1sh,g_bn1sh);
    cudaGetSymbolAddress((void**)&p_bn2s, g_bn2s);
    cudaGetSymbolAddress((void**)&p_bn2sh,g_bn2sh);

    cudaFuncSetAttribute(gemm_tc<1>, cudaFuncAttributeMaxDynamicSharedMemorySize, GEMM_SMEM_BYTES);
    cudaFuncSetAttribute(gemm_tc<2>, cudaFuncAttributeMaxDynamicSharedMemorySize, GEMM_SMEM_BYTES);
    cudaFuncSetAttribute(gemm_tc<3>, cudaFuncAttributeMaxDynamicSharedMemorySize, GEMM_SMEM_BYTES);
    cudaFuncSetAttribute(gemm_tc<4>, cudaFuncAttributeMaxDynamicSharedMemorySize, GEMM_SMEM_BYTES);

    // fork: KNN depends only on xyz -> run concurrently with prep + q/kv GEMM.
    // (stream/events created per call and leaked: only ~2-3 kernel_launch calls
    //  happen per run; no device memory is allocated.)
    cudaStream_t s2;
    cudaEvent_t eF, eJ;
    cudaStreamCreateWithFlags(&s2, cudaStreamNonBlocking);
    cudaEventCreateWithFlags(&eF, cudaEventDisableTiming);
    cudaEventCreateWithFlags(&eJ, cudaEventDisableTiming);

    cudaEventRecord(eF, 0);
    cudaStreamWaitEvent(s2, eF, 0);
    knn_kernel<<<BB*NN/8, 256, 0, s2>>>(xyz);
    cudaEventRecord(eJ, s2);

    prep_kernel<<<5, 256>>>(rp_g, rp_b, rp_m, rp_v, rp_w2,
                            bn1_g, bn1_b, bn1_m, bn1_v,
                            bn2_g, bn2_b, bn2_m, bn2_v);

    // fused qT/kvT = (Wq @ x)^T, (Wkv @ x)^T
    gemm_tc<4><<<dim3(NN/128, 6, BB), 256, GEMM_SMEM_BYTES>>>(
        Wq, x, p_qT, CC, CC, NN, nullptr, nullptr, nullptr, nullptr, Wkv, p_kvT);

    cudaStreamWaitEvent(0, eJ, 0);   // join knn before attention

    attn_kernel<<<BB*NN/8, 256>>>(xyz, rp_w1);

    // x1 = bn1(x + Wproj @ attn_out)
    gemm_tc<2><<<dim3(NN/128, CC/128, BB), 256, GEMM_SMEM_BYTES>>>(
        Wproj, p_ao, p_x1, CC, CC, NN, nullptr, x, p_bn1s, p_bn1sh, nullptr, nullptr);
    // h = relu(ffn_w1 @ x1 + b1)
    gemm_tc<1><<<dim3(NN/128, 4*CC/128, BB), 256, GEMM_SMEM_BYTES>>>(
        ffn_w1, p_x1, p_h, 4*CC, CC, NN, ffn_b1, nullptr, nullptr, nullptr, nullptr, nullptr);
    // out = bn2(x1 + ffn_w2 @ h + b2)
    gemm_tc<3><<<dim3(NN/128, CC/128, BB), 256, GEMM_SMEM_BYTES>>>(
        ffn_w2, p_h, out, CC, 4*CC, NN, ffn_b2, p_x1, p_bn2s, p_bn2sh, nullptr, nullptr);

    (void)in_sizes; (void)n_in; (void)out_size;
}

// round 5
// speedup vs baseline: 2.2065x; 1.0279x over previous
#include <cuda_runtime.h>
#include <math.h>

// Problem constants
#define BB 2
#define CC 256
#define NN 4096
#define HH 4
#define KK 16
#define DD 64
#define EPSBN 1e-5f
#define SCALE 0.125f   // d^-0.5 = 1/8

// ---------------- scratch (device globals; no allocation allowed) ----------------
__device__ float g_qT  [BB*NN*CC];        // qT  [B][N][C]
__device__ float g_kvT [BB*NN*2*CC];      // kvT [B][N][2C] (first C=k, next C=v)
__device__ float g_ao  [BB*CC*NN];        // attention output [B][C][N]
__device__ float g_x1  [BB*CC*NN];        // after bn1 [B][C][N]
__device__ float g_hbuf[BB*4*CC*NN];      // ffn hidden [B][4C][N]
__device__ int   g_nbr [BB*NN*KK];        // knn indices
__device__ float g_w2h [HH*CC];           // per-head column sums of rp_w2
__device__ float g_rps [CC], g_rpsh[CC];
__device__ float g_bn1s[CC], g_bn1sh[CC];
__device__ float g_bn2s[CC], g_bn2sh[CC];

// ---------------- helpers ----------------
__device__ __forceinline__ void mma_tf32(float c[4],
                                         const unsigned a[4],
                                         const unsigned b[2]) {
    asm volatile(
        "mma.sync.aligned.m16n8k8.row.col.f32.tf32.tf32.f32 "
        "{%0,%1,%2,%3}, {%4,%5,%6,%7}, {%8,%9}, {%0,%1,%2,%3};"
        : "+f"(c[0]), "+f"(c[1]), "+f"(c[2]), "+f"(c[3])
        : "r"(a[0]), "r"(a[1]), "r"(a[2]), "r"(a[3]),
          "r"(b[0]), "r"(b[1]));
}

__device__ __forceinline__ void cp16(unsigned* smem_dst, const float* gsrc) {
    unsigned u = (unsigned)__cvta_generic_to_shared(smem_dst);
    asm volatile("cp.async.cg.shared.global [%0], [%1], 16;" :: "r"(u), "l"(gsrc));
}

// ---------------- param prep (5 blocks) ----------------
__global__ void prep_kernel(const float* __restrict__ rp_g, const float* __restrict__ rp_b,
                            const float* __restrict__ rp_m, const float* __restrict__ rp_v,
                            const float* __restrict__ rp_w2,
                            const float* __restrict__ b1g, const float* __restrict__ b1b,
                            const float* __restrict__ b1m, const float* __restrict__ b1v,
                            const float* __restrict__ b2g, const float* __restrict__ b2b,
                            const float* __restrict__ b2m, const float* __restrict__ b2v)
{
    int t = threadIdx.x;
    int blk = blockIdx.x;
    if (blk < HH) {
        float acc = 0.f;
        #pragma unroll 8
        for (int o = 0; o < DD; o++)
            acc += rp_w2[(blk*DD + o)*CC + t];
        g_w2h[blk*CC + t] = acc;
    } else {
        float s = rp_g[t] * rsqrtf(rp_v[t] + EPSBN);
        g_rps[t]  = s;
        g_rpsh[t] = rp_b[t] - rp_m[t] * s;
        float s1 = b1g[t] * rsqrtf(b1v[t] + EPSBN);
        g_bn1s[t]  = s1;
        g_bn1sh[t] = b1b[t] - b1m[t] * s1;
        float s2 = b2g[t] * rsqrtf(b2v[t] + EPSBN);
        g_bn2s[t]  = s2;
        g_bn2sh[t] = b2b[t] - b2m[t] * s2;
    }
}

// ---------------- KNN: warp per query, warp-shared threshold + sorted insert ----------------
__global__ void knn_kernel(const float* __restrict__ xyz)
{
    int w = threadIdx.x >> 5, lane = threadIdx.x & 31;
    int g = blockIdx.x * 8 + w;
    int b = g >> 12, n = g & (NN - 1);
    const float* X = xyz + (size_t)b * 3 * NN;
    float qx = X[n], qy = X[NN + n], qz = X[2*NN + n];

    float bk[KK]; int bi[KK];          // sorted ascending; bk[15] = worst
    #pragma unroll
    for (int i = 0; i < KK; i++) { bk[i] = 1e30f; bi[i] = 0; }
    float W = 1e30f;

    for (int j = 0; j < NN/32; j++) {
        int m = lane + 32*j;
        float px = X[m], py = X[NN + m], pz = X[2*NN + m];
        float key = fmaf(px, px, fmaf(py, py, pz*pz))
                  - 2.f * fmaf(qx, px, fmaf(qy, py, qz*pz));
        if (__any_sync(0xffffffffu, key < W)) {
            if (key < W) {
                bk[KK-1] = key; bi[KK-1] = m;
                #pragma unroll
                for (int i = KK-1; i > 0; i--) {
                    float a = bk[i-1], c = bk[i];
                    int   ai = bi[i-1], ci = bi[i];
                    bool sw = c < a;
                    bk[i-1] = sw ? c : a;  bk[i] = sw ? a : c;
                    bi[i-1] = sw ? ci : ai; bi[i] = sw ? ai : ci;
                }
            }
            float wv = bk[KK-1];
            #pragma unroll
            for (int off = 16; off > 0; off >>= 1)
                wv = fminf(wv, __shfl_xor_sync(0xffffffffu, wv, off));
            W = wv;
        }
    }

    int myNbr = 0;
    for (int r = 0; r < KK; r++) {
        float mv = bk[0]; int pidx = bi[0]; int owner = lane;
        #pragma unroll
        for (int off = 16; off > 0; off >>= 1) {
            float ov = __shfl_xor_sync(0xffffffffu, mv, off);
            int   oi = __shfl_xor_sync(0xffffffffu, pidx, off);
            int   oo = __shfl_xor_sync(0xffffffffu, owner, off);
            if (ov < mv || (ov == mv && oo < owner)) { mv = ov; pidx = oi; owner = oo; }
        }
        if (lane == owner) {
            #pragma unroll
            for (int i = 0; i < KK-1; i++) { bk[i] = bk[i+1]; bi[i] = bi[i+1]; }
            bk[KK-1] = 1e30f;
        }
        if (lane == r) myNbr = pidx;
    }
    if (lane < KK) g_nbr[(size_t)g * KK + lane] = myNbr;
}

// ---------------- tf32 tensor-core GEMM, 3-stage cp.async, 1 sync/iter, 2 CTA/SM ----------------
// Y[b] = W(OxC) * X[b](CxN). 128x128 block tile, BK=32, 8 warps of 64x32.
// MODE 1: relu(acc+bias); 2: (resid+acc)*s+sh; 3: (acc+bias+resid)*s+sh;
// MODE 4: fused q/kv, transposed store via smem staging.
#define LDA 36
#define LDB 136
#define STAGE_WORDS (128*LDA + 32*LDB)
#define GEMM_SMEM_BYTES (3*STAGE_WORDS*4)

template<int MODE>
__global__ __launch_bounds__(256, 2)
void gemm_tc(const float* __restrict__ W, const float* __restrict__ X,
             float* __restrict__ Y, int O, int C, int Nn,
             const float* __restrict__ bias,
             const float* __restrict__ resid,
             const float* __restrict__ bns, const float* __restrict__ bnsh,
             const float* __restrict__ W2, float* __restrict__ Y2)
{
    extern __shared__ unsigned sm[];

    const int b = blockIdx.z;
    X += (size_t)b * C * Nn;

    const float* Wp;
    float* Yp;            // MODE 4 output base (batch included)
    int Ostr = 0, oB;
    if (MODE == 4) {
        int by = blockIdx.y;
        if (by < 2) { Wp = W;  Yp = Y  + (size_t)b * NN * CC;    Ostr = CC;    oB = by * 128; }
        else        { Wp = W2; Yp = Y2 + (size_t)b * NN * 2*CC;  Ostr = 2*CC;  oB = (by - 2) * 128; }
    } else {
        Wp = W; oB = blockIdx.y * 128;
        Y += (size_t)b * O * Nn;
        Yp = Y;
        if (MODE == 2 || MODE == 3) resid += (size_t)b * O * Nn;
    }

    const int tid   = threadIdx.x;
    const int lane  = tid & 31;
    const int wid   = tid >> 5;
    const int warpM = wid >> 2;          // 0..1
    const int warpN = wid & 3;           // 0..3
    const int lr    = lane >> 2;         // 0..7
    const int lc    = lane & 3;          // 0..3
    const int n0    = blockIdx.x * 128;

    const int arow = tid >> 3, akq = (tid & 7) * 4;     // +32 rows per i
    const int brow = tid >> 5, bnq = (tid & 31) * 4;    // +8 rows per i

    float acc[4][4][4];
    #pragma unroll
    for (int mt = 0; mt < 4; mt++)
        #pragma unroll
        for (int nt = 0; nt < 4; nt++)
            #pragma unroll
            for (int r = 0; r < 4; r++) acc[mt][nt][r] = 0.f;

    const int ntiles = C >> 5;

    // prologue: stages 0,1
    #pragma unroll
    for (int p = 0; p < 2; p++) {
        unsigned* As = sm + p*STAGE_WORDS; unsigned* Bs = As + 128*LDA;
        int kt = p << 5;
        #pragma unroll
        for (int i = 0; i < 4; i++)
            cp16(&As[(arow + 32*i) * LDA + akq], &Wp[(size_t)(oB + arow + 32*i) * C + kt + akq]);
        #pragma unroll
        for (int i = 0; i < 4; i++)
            cp16(&Bs[(brow + 8*i) * LDB + bnq], &X[(size_t)(kt + brow + 8*i) * Nn + n0 + bnq]);
        asm volatile("cp.async.commit_group;");
    }

    int sNext = 2;   // stage slot for it+2
    for (int it = 0; it < ntiles; it++) {
        asm volatile("cp.async.wait_group %0;" :: "n"(1));
        __syncthreads();

        if (it + 2 < ntiles) {
            int ktn = (it + 2) << 5;
            unsigned* As = sm + sNext*STAGE_WORDS; unsigned* Bs = As + 128*LDA;
            #pragma unroll
            for (int i = 0; i < 4; i++)
                cp16(&As[(arow + 32*i) * LDA + akq], &Wp[(size_t)(oB + arow + 32*i) * C + ktn + akq]);
            #pragma unroll
            for (int i = 0; i < 4; i++)
                cp16(&Bs[(brow + 8*i) * LDB + bnq], &X[(size_t)(ktn + brow + 8*i) * Nn + n0 + bnq]);
        }
        asm volatile("cp.async.commit_group;");

        int sCur = sNext + 1; if (sCur >= 3) sCur -= 3;   // == it % 3
        const unsigned* As = sm + sCur*STAGE_WORDS;
        const unsigned* Bs = As + 128*LDA;
        #pragma unroll
        for (int kk = 0; kk < 4; kk++) {
            const int kb = kk * 8;
            unsigned afr[4][4], bfr[4][2];
            #pragma unroll
            for (int mt = 0; mt < 4; mt++) {
                int r = warpM * 64 + mt * 16 + lr;
                afr[mt][0] = As[r       * LDA + kb + lc];
                afr[mt][1] = As[(r + 8) * LDA + kb + lc];
                afr[mt][2] = As[r       * LDA + kb + 4 + lc];
                afr[mt][3] = As[(r + 8) * LDA + kb + 4 + lc];
            }
            #pragma unroll
            for (int nt = 0; nt < 4; nt++) {
                int cb = warpN * 32 + nt * 8 + lr;
                bfr[nt][0] = Bs[(kb + lc)     * LDB + cb];
                bfr[nt][1] = Bs[(kb + 4 + lc) * LDB + cb];
            }
            #pragma unroll
            for (int mt = 0; mt < 4; mt++)
                #pragma unroll
                for (int nt = 0; nt < 4; nt++)
                    mma_tf32(acc[mt][nt], afr[mt], bfr[nt]);
        }
        sNext = sCur;
    }

    if (MODE == 4) {
        // stage tile in smem, then coalesced float4 row stores of [n][o]
        __syncthreads();
        float* stg = reinterpret_cast<float*>(sm);   // [128][132]
        #pragma unroll
        for (int mt = 0; mt < 4; mt++) {
            int ol = warpM * 64 + mt * 16 + lr;
            #pragma unroll
            for (int nt = 0; nt < 4; nt++) {
                int nl = warpN * 32 + nt * 8 + lc * 2;
                stg[nl      * 132 + ol]     = acc[mt][nt][0];
                stg[(nl + 1)* 132 + ol]     = acc[mt][nt][1];
                stg[nl      * 132 + ol + 8] = acc[mt][nt][2];
                stg[(nl + 1)* 132 + ol + 8] = acc[mt][nt][3];
            }
        }
        __syncthreads();
        #pragma unroll
        for (int r = wid; r < 128; r += 8) {
            float4 v = *reinterpret_cast<float4*>(&stg[r * 132 + lane * 4]);
            *reinterpret_cast<float4*>(&Yp[(size_t)(n0 + r) * Ostr + oB + lane * 4]) = v;
        }
        return;
    }

    // epilogue (MODE 1/2/3)
    #pragma unroll
    for (int mt = 0; mt < 4; mt++) {
        int o = oB + warpM * 64 + mt * 16 + lr;
        #pragma unroll
        for (int nt = 0; nt < 4; nt++) {
            int n = n0 + warpN * 32 + nt * 8 + lc * 2;
            float2 p0 = make_float2(acc[mt][nt][0], acc[mt][nt][1]);
            float2 p1 = make_float2(acc[mt][nt][2], acc[mt][nt][3]);
            size_t i0 = (size_t)o * Nn + n;
            size_t i1 = (size_t)(o + 8) * Nn + n;
            if (MODE == 1) {
                float b0 = bias[o], b1 = bias[o + 8];
                p0.x = fmaxf(p0.x + b0, 0.f); p0.y = fmaxf(p0.y + b0, 0.f);
                p1.x = fmaxf(p1.x + b1, 0.f); p1.y = fmaxf(p1.y + b1, 0.f);
            } else if (MODE == 2) {
                float s0 = bns[o], h0 = bnsh[o];
                float s1 = bns[o + 8], h1 = bnsh[o + 8];
                float2 r0 = *reinterpret_cast<const float2*>(&resid[i0]);
                float2 r1 = *reinterpret_cast<const float2*>(&resid[i1]);
                p0.x = (p0.x + r0.x) * s0 + h0; p0.y = (p0.y + r0.y) * s0 + h0;
                p1.x = (p1.x + r1.x) * s1 + h1; p1.y = (p1.y + r1.y) * s1 + h1;
            } else if (MODE == 3) {
                float s0 = bns[o], h0 = bnsh[o], bo0 = bias[o];
                float s1 = bns[o + 8], h1 = bnsh[o + 8], bo1 = bias[o + 8];
                float2 r0 = *reinterpret_cast<const float2*>(&resid[i0]);
                float2 r1 = *reinterpret_cast<const float2*>(&resid[i1]);
                p0.x = (p0.x + bo0 + r0.x) * s0 + h0; p0.y = (p0.y + bo0 + r0.y) * s0 + h0;
                p1.x = (p1.x + bo1 + r1.x) * s1 + h1; p1.y = (p1.y + bo1 + r1.y) * s1 + h1;
            }
            *reinterpret_cast<float2*>(&Yp[i0]) = p0;
            *reinterpret_cast<float2*>(&Yp[i1]) = p1;
        }
    }
}

// ---------------- attention (warp per point, butterfly multi-head reduce) ----------------
__global__ __launch_bounds__(256)
void attn_kernel(const float* __restrict__ xyz, const float* __restrict__ rp_w1)
{
    __shared__ int   sIdx[8][KK];
    __shared__ float sLog[8][HH][KK];
    __shared__ float sOut[CC][9];

    int w = threadIdx.x >> 5, lane = threadIdx.x & 31;
    int g = blockIdx.x * 8 + w;
    int b = g >> 12, n = g & (NN - 1);

    if (lane < KK) sIdx[w][lane] = g_nbr[(size_t)g * KK + lane];
    __syncwarp();

    float qreg[8], w1x[8], w1y[8], w1z[8], rps[8], rpsh[8], w2r[HH][8];
    #pragma unroll
    for (int j = 0; j < 8; j++) {
        int c = lane + 32*j;
        qreg[j] = g_qT[(size_t)g * CC + c];
        w1x[j] = rp_w1[c*3 + 0];
        w1y[j] = rp_w1[c*3 + 1];
        w1z[j] = rp_w1[c*3 + 2];
        rps[j]  = g_rps[c];
        rpsh[j] = g_rpsh[c];
        #pragma unroll
        for (int h = 0; h < HH; h++) w2r[h][j] = g_w2h[h*CC + c];
    }
    const float* Xp = xyz + (size_t)b * 3 * NN;
    float cx = Xp[n], cy = Xp[NN + n], cz = Xp[2*NN + n];

    const bool hi = lane >= 16;
    const bool b8 = (lane & 8) != 0;

    for (int k = 0; k < KK; k++) {
        int m = sIdx[w][k];
        float rx = Xp[m] - cx, ry = Xp[NN + m] - cy, rz = Xp[2*NN + m] - cz;
        const float* kvp = &g_kvT[((size_t)b * NN + m) * (2*CC)];
        float qk[HH]  = {0.f, 0.f, 0.f, 0.f};
        float bia[HH] = {0.f, 0.f, 0.f, 0.f};
        #pragma unroll
        for (int j = 0; j < 8; j++) {
            float kv = kvp[lane + 32*j];
            qk[j >> 1] = fmaf(qreg[j], kv, qk[j >> 1]);
            float raw = fmaf(w1x[j], rx, fmaf(w1y[j], ry, w1z[j]*rz));
            float h1 = fmaxf(fmaf(raw, rps[j], rpsh[j]), 0.f);
            #pragma unroll
            for (int h = 0; h < HH; h++)
                bia[h] = fmaf(w2r[h][j], h1, bia[h]);
        }
        float t4[HH];
        #pragma unroll
        for (int h = 0; h < HH; h++) t4[h] = fmaf(SCALE, qk[h], bia[h]);

        // butterfly: fold heads into lane groups. after r1: lanes<16 hold h0,h1
        // partials; lanes>=16 hold h2,h3. after r2: lane&8 selects h1/h3 vs h0/h2.
        float s0 = hi ? t4[2] : t4[0];
        float o0 = hi ? t4[0] : t4[2];
        float s1 = hi ? t4[3] : t4[1];
        float o1 = hi ? t4[1] : t4[3];
        s0 += __shfl_xor_sync(0xffffffffu, o0, 16);
        s1 += __shfl_xor_sync(0xffffffffu, o1, 16);
        float sA = b8 ? s1 : s0;
        float oA = b8 ? s0 : s1;
        sA += __shfl_xor_sync(0xffffffffu, oA, 8);
        sA += __shfl_xor_sync(0xffffffffu, sA, 4);
        sA += __shfl_xor_sync(0xffffffffu, sA, 2);
        sA += __shfl_xor_sync(0xffffffffu, sA, 1);
        // lanes 0-7: h0, 8-15: h1, 16-23: h2, 24-31: h3 (replicated within group)
        if ((lane & 7) == 0) sLog[w][lane >> 3][k] = sA;
    }
    __syncwarp();

    if (lane < HH) {
        float mx = -1e30f;
        #pragma unroll
        for (int k = 0; k < KK; k++) mx = fmaxf(mx, sLog[w][lane][k]);
        float s = 0.f;
        #pragma unroll
        for (int k = 0; k < KK; k++) {
            float e = __expf(sLog[w][lane][k] - mx);
            sLog[w][lane][k] = e;
            s += e;
        }
        float inv = 1.f / s;
        #pragma unroll
        for (int k = 0; k < KK; k++) sLog[w][lane][k] *= inv;
    }
    __syncwarp();

    float acc[8] = {0,0,0,0,0,0,0,0};
    for (int k = 0; k < KK; k++) {
        int m = sIdx[w][k];
        const float* vp = &g_kvT[((size_t)b * NN + m) * (2*CC) + CC];
        #pragma unroll
        for (int j = 0; j < 8; j++)
            acc[j] = fmaf(sLog[w][j >> 1][k], vp[lane + 32*j], acc[j]);
    }
    #pragma unroll
    for (int j = 0; j < 8; j++) sOut[lane + 32*j][w] = acc[j];
    __syncthreads();

    int t = threadIdx.x;
    int bb = (blockIdx.x * 8) >> 12;
    int n0 = (blockIdx.x * 8) & (NN - 1);
    float4 v0 = make_float4(sOut[t][0], sOut[t][1], sOut[t][2], sOut[t][3]);
    float4 v1 = make_float4(sOut[t][4], sOut[t][5], sOut[t][6], sOut[t][7]);
    float* op = &g_ao[((size_t)bb * CC + t) * NN + n0];
    *reinterpret_cast<float4*>(op)     = v0;
    *reinterpret_cast<float4*>(op + 4) = v1;
}

// ---------------- launch ----------------
extern "C" void kernel_launch(void* const* d_in, const int* in_sizes, int n_in,
                              void* d_out, int out_size)
{
    const float* x      = (const float*)d_in[0];
    const float* xyz    = (const float*)d_in[1];
    const float* Wq     = (const float*)d_in[2];
    const float* Wkv    = (const float*)d_in[3];
    const float* Wproj  = (const float*)d_in[4];
    const float* rp_w1  = (const float*)d_in[5];
    const float* rp_g   = (const float*)d_in[6];
    const float* rp_b   = (const float*)d_in[7];
    const float* rp_m   = (const float*)d_in[8];
    const float* rp_v   = (const float*)d_in[9];
    const float* rp_w2  = (const float*)d_in[10];
    const float* bn1_g  = (const float*)d_in[11];
    const float* bn1_b  = (const float*)d_in[12];
    const float* bn1_m  = (const float*)d_in[13];
    const float* bn1_v  = (const float*)d_in[14];
    const float* bn2_g  = (const float*)d_in[15];
    const float* bn2_b  = (const float*)d_in[16];
    const float* bn2_m  = (const float*)d_in[17];
    const float* bn2_v  = (const float*)d_in[18];
    const float* ffn_w1 = (const float*)d_in[19];
    const float* ffn_b1 = (const float*)d_in[20];
    const float* ffn_w2 = (const float*)d_in[21];
    const float* ffn_b2 = (const float*)d_in[22];
    float* out = (float*)d_out;

    float *p_qT, *p_kvT, *p_ao, *p_x1, *p_h;
    float *p_bn1s, *p_bn1sh, *p_bn2s, *p_bn2sh;
    cudaGetSymbolAddress((void**)&p_qT,   g_qT);
    cudaGetSymbolAddress((void**)&p_kvT,  g_kvT);
    cudaGetSymbolAddress((void**)&p_ao,   g_ao);
    cudaGetSymbolAddress((void**)&p_x1,   g_x1);
    cudaGetSymbolAddress((void**)&p_h,    g_hbuf);
    cudaGetSymbolAddress((void**)&p_bn1s, g_bn1s);
    cudaGetSymbolAddress((void**)&p_bn1sh,g_bn1sh);
    cudaGetSymbolAddress((void**)&p_bn2s, g_bn2s);
    cudaGetSymbolAddress((void**)&p_bn2sh,g_bn2sh);

    cudaFuncSetAttribute(gemm_tc<1>, cudaFuncAttributeMaxDynamicSharedMemorySize, GEMM_SMEM_BYTES);
    cudaFuncSetAttribute(gemm_tc<2>, cudaFuncAttributeMaxDynamicSharedMemorySize, GEMM_SMEM_BYTES);
    cudaFuncSetAttribute(gemm_tc<3>, cudaFuncAttributeMaxDynamicSharedMemorySize, GEMM_SMEM_BYTES);
    cudaFuncSetAttribute(gemm_tc<4>, cudaFuncAttributeMaxDynamicSharedMemorySize, GEMM_SMEM_BYTES);

    // fork: KNN depends only on xyz -> run concurrently with prep + q/kv GEMM.
    cudaStream_t s2;
    cudaEvent_t eF, eJ;
    cudaStreamCreateWithFlags(&s2, cudaStreamNonBlocking);
    cudaEventCreateWithFlags(&eF, cudaEventDisableTiming);
    cudaEventCreateWithFlags(&eJ, cudaEventDisableTiming);

    cudaEventRecord(eF, 0);
    cudaStreamWaitEvent(s2, eF, 0);
    knn_kernel<<<BB*NN/8, 256, 0, s2>>>(xyz);
    cudaEventRecord(eJ, s2);

    prep_kernel<<<5, 256>>>(rp_g, rp_b, rp_m, rp_v, rp_w2,
                            bn1_g, bn1_b, bn1_m, bn1_v,
                            bn2_g, bn2_b, bn2_m, bn2_v);

    // fused qT/kvT = (Wq @ x)^T, (Wkv @ x)^T
    gemm_tc<4><<<dim3(NN/128, 6, BB), 256, GEMM_SMEM_BYTES>>>(
        Wq, x, p_qT, CC, CC, NN, nullptr, nullptr, nullptr, nullptr, Wkv, p_kvT);

    cudaStreamWaitEvent(0, eJ, 0);   // join knn before attention

    attn_kernel<<<BB*NN/8, 256>>>(xyz, rp_w1);

    // x1 = bn1(x + Wproj @ attn_out)
    gemm_tc<2><<<dim3(NN/128, CC/128, BB), 256, GEMM_SMEM_BYTES>>>(
        Wproj, p_ao, p_x1, CC, CC, NN, nullptr, x, p_bn1s, p_bn1sh, nullptr, nullptr);
    // h = relu(ffn_w1 @ x1 + b1)
    gemm_tc<1><<<dim3(NN/128, 4*CC/128, BB), 256, GEMM_SMEM_BYTES>>>(
        ffn_w1, p_x1, p_h, 4*CC, CC, NN, ffn_b1, nullptr, nullptr, nullptr, nullptr, nullptr);
    // out = bn2(x1 + ffn_w2 @ h + b2)
    gemm_tc<3><<<dim3(NN/128, CC/128, BB), 256, GEMM_SMEM_BYTES>>>(
        ffn_w2, p_h, out, CC, 4*CC, NN, ffn_b2, p_x1, p_bn2s, p_bn2sh, nullptr, nullptr);

    (void)in_sizes; (void)n_in; (void)out_size;
}